// round 4
// baseline (speedup 1.0000x reference)
#include <cuda_runtime.h>
#include <math.h>

#define B_ 8
#define S_ 1024
#define D_ 1024
#define NH_ 16
#define NKV_ 8
#define HD_ 64

// Scratch (allocation-free rule: __device__ globals)
__device__ float g_q[B_*S_*NH_*HD_];    // 32 MB
__device__ float g_k[B_*S_*NKV_*HD_];   // 16 MB
__device__ float g_v[B_*S_*NKV_*HD_];   // 16 MB
__device__ float g_ao[B_*S_*NH_*HD_];   // 32 MB

// ---------------------------------------------------------------------------
// SGEMM: C[M,N] = A[M,K] @ B[K,N], all row-major, fp32.
// 128x128 tile, BK=16, 256 threads, 8x8 microtile per thread.
// Requires M%128==0, N%128==0, K%16==0 (true for all 4 calls).
// ---------------------------------------------------------------------------
__global__ __launch_bounds__(256) void sgemm128(const float* __restrict__ A,
                                                const float* __restrict__ Bm,
                                                float* __restrict__ C,
                                                int M, int N, int K)
{
    __shared__ float As[16][128];
    __shared__ float Bs[16][128];

    const int tid = threadIdx.x;
    const int bm = blockIdx.y;
    const int bn = blockIdx.x;

    const float* Ablk = A + (size_t)bm * 128 * K;
    const float* Bblk = Bm + (size_t)bn * 128;

    // A-tile load mapping: 128 rows x 16 cols = 512 float4, 2 per thread
    const int arow = tid >> 2;            // 0..63
    const int ac4  = (tid & 3) * 4;       // 0,4,8,12
    // B-tile load mapping: 16 rows x 128 cols = 512 float4, 2 per thread
    const int brow = tid >> 5;            // 0..7
    const int bc4  = (tid & 31) * 4;      // 0..124

    const int ty = tid >> 4;              // 0..15  (row group)
    const int tx = tid & 15;              // 0..15  (col group)

    float acc[8][8];
#pragma unroll
    for (int i = 0; i < 8; i++)
#pragma unroll
        for (int j = 0; j < 8; j++) acc[i][j] = 0.f;

    for (int k0 = 0; k0 < K; k0 += 16) {
        float4 a0 = *(const float4*)(Ablk + (size_t)arow * K + k0 + ac4);
        float4 a1 = *(const float4*)(Ablk + (size_t)(arow + 64) * K + k0 + ac4);
        float4 b0 = *(const float4*)(Bblk + (size_t)(k0 + brow) * N + bc4);
        float4 b1 = *(const float4*)(Bblk + (size_t)(k0 + brow + 8) * N + bc4);

        __syncthreads();   // previous iteration's readers done

        As[ac4 + 0][arow] = a0.x; As[ac4 + 1][arow] = a0.y;
        As[ac4 + 2][arow] = a0.z; As[ac4 + 3][arow] = a0.w;
        As[ac4 + 0][arow + 64] = a1.x; As[ac4 + 1][arow + 64] = a1.y;
        As[ac4 + 2][arow + 64] = a1.z; As[ac4 + 3][arow + 64] = a1.w;
        *(float4*)&Bs[brow][bc4]     = b0;
        *(float4*)&Bs[brow + 8][bc4] = b1;

        __syncthreads();

#pragma unroll
        for (int k = 0; k < 16; k++) {
            float ar[8], br[8];
            float4 t0 = *(const float4*)&As[k][ty * 8];
            float4 t1 = *(const float4*)&As[k][ty * 8 + 4];
            ar[0]=t0.x; ar[1]=t0.y; ar[2]=t0.z; ar[3]=t0.w;
            ar[4]=t1.x; ar[5]=t1.y; ar[6]=t1.z; ar[7]=t1.w;
            float4 u0 = *(const float4*)&Bs[k][tx * 8];
            float4 u1 = *(const float4*)&Bs[k][tx * 8 + 4];
            br[0]=u0.x; br[1]=u0.y; br[2]=u0.z; br[3]=u0.w;
            br[4]=u1.x; br[5]=u1.y; br[6]=u1.z; br[7]=u1.w;
#pragma unroll
            for (int i = 0; i < 8; i++)
#pragma unroll
                for (int j = 0; j < 8; j++)
                    acc[i][j] = fmaf(ar[i], br[j], acc[i][j]);
        }
    }

#pragma unroll
    for (int i = 0; i < 8; i++) {
        float* crow = C + (size_t)(bm * 128 + ty * 8 + i) * N + bn * 128 + tx * 8;
        float4 o0 = {acc[i][0], acc[i][1], acc[i][2], acc[i][3]};
        float4 o1 = {acc[i][4], acc[i][5], acc[i][6], acc[i][7]};
        *(float4*)(crow)     = o0;
        *(float4*)(crow + 4) = o1;
    }
}

// ---------------------------------------------------------------------------
// RoPE (interleaved pairs). Memory layout [B,S,nh,64]; pair p covers elements
// 2p, 2p+1 in row-major pair order, so addressing is direct.
// ---------------------------------------------------------------------------
__global__ void rope_kernel(float* __restrict__ x,
                            const float* __restrict__ cs,
                            const float* __restrict__ sn,
                            int nh, int total_pairs)
{
    int p = blockIdx.x * blockDim.x + threadIdx.x;
    if (p >= total_pairs) return;
    int d2 = p & 31;
    int s  = (p / (32 * nh)) & (S_ - 1);
    float c  = cs[s * 32 + d2];
    float si = sn[s * 32 + d2];
    float2 xv = *(float2*)(x + (size_t)p * 2);
    float2 r;
    r.x = xv.x * c - xv.y * si;
    r.y = xv.x * si + xv.y * c;
    *(float2*)(x + (size_t)p * 2) = r;
}

// ---------------------------------------------------------------------------
// Flash attention with block-causal mask (block size 8), GQA rep=2.
// Grid: (S/128, NH, B). 128 threads; thread t owns query row blockIdx.x*128+t.
// K/V tiles of 32 keys staged in smem; smem reads are warp-broadcast.
// Key tiles kt < 4*qt are fully visible; kt in [4qt, 4qt+3] are predicated.
// ---------------------------------------------------------------------------
__global__ __launch_bounds__(128) void attn_kernel(const float* __restrict__ q,
                                                   const float* __restrict__ k,
                                                   const float* __restrict__ v,
                                                   float* __restrict__ out)
{
    const int qt  = blockIdx.x;
    const int h   = blockIdx.y;
    const int b   = blockIdx.z;
    const int kvh = h >> 1;
    const int tid = threadIdx.x;
    const int i   = qt * 128 + tid;          // query index
    const int qblk = i >> 3;

    __shared__ float ks[32][64];
    __shared__ float vs[32][64];

    float qr[64];
    const float* qptr = q + (((size_t)(b * S_ + i) * NH_) + h) * HD_;
#pragma unroll
    for (int d = 0; d < 64; d += 4) {
        float4 t = *(const float4*)(qptr + d);
        qr[d] = t.x; qr[d+1] = t.y; qr[d+2] = t.z; qr[d+3] = t.w;
    }

    float m = -1e30f, l = 0.f;
    float acc[64];
#pragma unroll
    for (int d = 0; d < 64; d++) acc[d] = 0.f;

    const int ntiles = 4 * qt + 4;
    for (int kt = 0; kt < ntiles; kt++) {
        const float* kbase = k + (((size_t)(b * S_ + kt * 32) * NKV_) + kvh) * HD_;
        const float* vbase = v + (((size_t)(b * S_ + kt * 32) * NKV_) + kvh) * HD_;
        // 32 keys x 64 floats = 512 float4; 128 threads -> 4 each (x2 for K,V)
#pragma unroll
        for (int idx = tid; idx < 32 * 16; idx += 128) {
            int row = idx >> 4;
            int c4  = (idx & 15) * 4;
            *(float4*)&ks[row][c4] = *(const float4*)(kbase + (size_t)row * (NKV_ * HD_) + c4);
            *(float4*)&vs[row][c4] = *(const float4*)(vbase + (size_t)row * (NKV_ * HD_) + c4);
        }
        __syncthreads();

        const bool diag = (kt >= 4 * qt);
        float s[32];
        float tmax = -1e30f;
#pragma unroll
        for (int j = 0; j < 32; j++) {
            float sc = 0.f;
#pragma unroll
            for (int d = 0; d < 64; d++) sc = fmaf(qr[d], ks[j][d], sc);
            sc *= 0.125f;   // 1/sqrt(64)
            if (diag) {
                int jg = kt * 32 + j;
                if ((jg >> 3) > qblk) sc = -1e30f;
            }
            s[j] = sc;
            tmax = fmaxf(tmax, sc);
        }

        float mnew  = fmaxf(m, tmax);
        float alpha = __expf(m - mnew);
        l *= alpha;
#pragma unroll
        for (int d = 0; d < 64; d++) acc[d] *= alpha;
#pragma unroll
        for (int j = 0; j < 32; j++) {
            float p = __expf(s[j] - mnew);
            l += p;
#pragma unroll
            for (int d = 0; d < 64; d++) acc[d] = fmaf(p, vs[j][d], acc[d]);
        }
        m = mnew;
        __syncthreads();
    }

    const float inv = 1.f / l;
    float* optr = out + (((size_t)(b * S_ + i) * NH_) + h) * HD_;
#pragma unroll
    for (int d = 0; d < 64; d += 4) {
        float4 o = {acc[d] * inv, acc[d+1] * inv, acc[d+2] * inv, acc[d+3] * inv};
        *(float4*)(optr + d) = o;
    }
}

// ---------------------------------------------------------------------------
extern "C" void kernel_launch(void* const* d_in, const int* in_sizes, int n_in,
                              void* d_out, int out_size)
{
    const float* x   = (const float*)d_in[0];
    const float* wq  = (const float*)d_in[1];
    const float* wk  = (const float*)d_in[2];
    const float* wv  = (const float*)d_in[3];
    const float* wo  = (const float*)d_in[4];
    const float* fcc = (const float*)d_in[5];
    const float* fcs = (const float*)d_in[6];
    (void)in_sizes; (void)n_in;

    float *q, *k, *v, *ao;
    cudaGetSymbolAddress((void**)&q,  g_q);
    cudaGetSymbolAddress((void**)&k,  g_k);
    cudaGetSymbolAddress((void**)&v,  g_v);
    cudaGetSymbolAddress((void**)&ao, g_ao);

    const int M = B_ * S_;   // 8192

    // QKV projections
    sgemm128<<<dim3(NH_*HD_/128, M/128), 256>>>(x, wq, q, M, NH_*HD_, D_);
    sgemm128<<<dim3(NKV_*HD_/128, M/128), 256>>>(x, wk, k, M, NKV_*HD_, D_);
    sgemm128<<<dim3(NKV_*HD_/128, M/128), 256>>>(x, wv, v, M, NKV_*HD_, D_);

    // RoPE on q and k
    {
        int qp = B_ * S_ * NH_ * (HD_ / 2);
        int kp = B_ * S_ * NKV_ * (HD_ / 2);
        rope_kernel<<<(qp + 255) / 256, 256>>>(q, fcc, fcs, NH_, qp);
        rope_kernel<<<(kp + 255) / 256, 256>>>(k, fcc, fcs, NKV_, kp);
    }

    // Attention
    attn_kernel<<<dim3(S_/128, NH_, B_), 128>>>(q, k, v, ao);

    // Output projection -> d_out
    sgemm128<<<dim3(D_/128, M/128), 256>>>(ao, wo, (float*)d_out, M, D_, D_);
    (void)out_size;
}

// round 8
// speedup vs baseline: 1.2284x; 1.2284x over previous
#include <cuda_runtime.h>
#include <cuda_bf16.h>
#include <math.h>
#include <stdint.h>

#define B_ 8
#define S_ 1024
#define D_ 1024
#define NH_ 16
#define NKV_ 8
#define HD_ 64

// Scratch (allocation-free rule: __device__ globals)
__device__ float g_q[B_*S_*NH_*HD_];    // 32 MB
__device__ float g_k[B_*S_*NKV_*HD_];   // 16 MB
__device__ float g_v[B_*S_*NKV_*HD_];   // 16 MB
__device__ float g_ao[B_*S_*NH_*HD_];   // 32 MB

// ---------------------------------------------------------------------------
// helpers
// ---------------------------------------------------------------------------
__device__ __forceinline__ uint32_t smem_u32(const void* p) {
    uint32_t a;
    asm("{ .reg .u64 t; cvta.to.shared.u64 t, %1; cvt.u32.u64 %0, t; }" : "=r"(a) : "l"(p));
    return a;
}

__device__ __forceinline__ void ldsm_x4(uint32_t addr, uint32_t* d) {
    asm volatile("ldmatrix.sync.aligned.m8n8.x4.shared.b16 {%0,%1,%2,%3}, [%4];"
                 : "=r"(d[0]), "=r"(d[1]), "=r"(d[2]), "=r"(d[3]) : "r"(addr));
}

__device__ __forceinline__ void mma_bf16(float* c, const uint32_t* a, const uint32_t* b) {
    asm volatile(
        "mma.sync.aligned.m16n8k16.row.col.f32.bf16.bf16.f32 "
        "{%0,%1,%2,%3}, {%4,%5,%6,%7}, {%8,%9}, {%0,%1,%2,%3};"
        : "+f"(c[0]), "+f"(c[1]), "+f"(c[2]), "+f"(c[3])
        : "r"(a[0]), "r"(a[1]), "r"(a[2]), "r"(a[3]), "r"(b[0]), "r"(b[1]));
}

__device__ __forceinline__ uint32_t pk_bf2(float lo, float hi) {
    __nv_bfloat162 t;
    t.x = __float2bfloat16(lo);
    t.y = __float2bfloat16(hi);
    return *reinterpret_cast<uint32_t*>(&t);
}
__device__ __forceinline__ float bf_hi(float x, float* rem) {
    __nv_bfloat16 h = __float2bfloat16(x);
    float hf = __bfloat162float(h);
    *rem = x - hf;
    return hf;
}

// ---------------------------------------------------------------------------
// HMMA GEMM: C[M,N] = A[M,K] @ W[K,N], fp32 in/out, hi/lo bf16 split
// (3 mma passes: AhBh + AhBl + AlBh -> ~fp32 accuracy).
// Tile 128x128, BK=32, 256 threads (8 warps = 2m x 4n, 64x32 each).
// Requires M%128==0, N%128==0, K%32==0.
// smem: A/W tiles as bf16 [128][40] (pad 40 -> conflict-free ldmatrix),
// W staged transposed [n][k] so B frags use non-trans ldmatrix.
// ---------------------------------------------------------------------------
#define LDPAD 40

__global__ __launch_bounds__(256, 1) void hgemm(const float* __restrict__ A,
                                                const float* __restrict__ W,
                                                float* __restrict__ C,
                                                int N, int K)
{
    __shared__ __align__(16) __nv_bfloat16 sAh[128][LDPAD];
    __shared__ __align__(16) __nv_bfloat16 sAl[128][LDPAD];
    __shared__ __align__(16) __nv_bfloat16 sBh[128][LDPAD];
    __shared__ __align__(16) __nv_bfloat16 sBl[128][LDPAD];

    const int tid = threadIdx.x, lane = tid & 31, wid = tid >> 5;
    const int bn = blockIdx.x, bm = blockIdx.y;
    const int warp_m = (wid & 1) * 64;
    const int warp_n = (wid >> 1) * 32;

    // global load mapping
    const int arow = tid >> 1;            // 0..127
    const int ahalf = tid & 1;            // 16 cols each
    const float* Ap = A + (size_t)(bm * 128 + arow) * K + ahalf * 16;
    const int bnrow = tid & 127;          // n within tile
    const int kg = (tid >> 7) * 16;       // k-group
    const float* Wp = W + (size_t)bn * 128 + bnrow;

    // ldmatrix lane address offsets (bytes)
    const int g = lane >> 3, r = lane & 7;
    const uint32_t uAh = smem_u32(sAh), uAl = smem_u32(sAl);
    const uint32_t uBh = smem_u32(sBh), uBl = smem_u32(sBl);
    uint32_t aoff[4], boff[2];
#pragma unroll
    for (int mt = 0; mt < 4; mt++)
        aoff[mt] = ((warp_m + mt * 16 + (g & 1) * 8 + r) * LDPAD + (g >> 1) * 8) * 2;
#pragma unroll
    for (int nt2 = 0; nt2 < 2; nt2++)
        boff[nt2] = ((warp_n + nt2 * 16 + (g >> 1) * 8 + r) * LDPAD + (g & 1) * 8) * 2;

    float acc[4][4][4];
#pragma unroll
    for (int i = 0; i < 4; i++)
#pragma unroll
        for (int j = 0; j < 4; j++)
#pragma unroll
            for (int t = 0; t < 4; t++) acc[i][j][t] = 0.f;

    const int NCH = K / 32;
    for (int ch = 0; ch < NCH; ch++) {
        const int k0g = ch * 32;

        // global loads into regs (overlap with previous chunk's mma)
        float4 av[4];
#pragma unroll
        for (int i = 0; i < 4; i++)
            av[i] = *(const float4*)(Ap + k0g + i * 4);
        float bv[16];
#pragma unroll
        for (int j = 0; j < 16; j++)
            bv[j] = Wp[(size_t)(k0g + kg + j) * N];

        __syncthreads();   // previous compute done reading smem

        // STS A hi/lo
#pragma unroll
        for (int i = 0; i < 4; i++) {
            float r0, r1, r2, r3;
            float h0 = bf_hi(av[i].x, &r0), h1 = bf_hi(av[i].y, &r1);
            float h2 = bf_hi(av[i].z, &r2), h3 = bf_hi(av[i].w, &r3);
            int c0 = ahalf * 16 + i * 4;
            *(uint2*)&sAh[arow][c0] = make_uint2(pk_bf2(h0, h1), pk_bf2(h2, h3));
            *(uint2*)&sAl[arow][c0] = make_uint2(pk_bf2(r0, r1), pk_bf2(r2, r3));
        }
        // STS B hi/lo (transposed: [n][k])
#pragma unroll
        for (int jb = 0; jb < 4; jb++) {
            float r0, r1, r2, r3;
            float h0 = bf_hi(bv[jb*4+0], &r0), h1 = bf_hi(bv[jb*4+1], &r1);
            float h2 = bf_hi(bv[jb*4+2], &r2), h3 = bf_hi(bv[jb*4+3], &r3);
            int c0 = kg + jb * 4;
            *(uint2*)&sBh[bnrow][c0] = make_uint2(pk_bf2(h0, h1), pk_bf2(h2, h3));
            *(uint2*)&sBl[bnrow][c0] = make_uint2(pk_bf2(r0, r1), pk_bf2(r2, r3));
        }
        __syncthreads();

        // 3 passes x 2 k16-steps
#pragma unroll
        for (int p = 0; p < 3; p++) {
            const uint32_t ua = (p == 2) ? uAl : uAh;
            const uint32_t ub = (p == 1) ? uBl : uBh;
#pragma unroll
            for (int ks = 0; ks < 2; ks++) {
                const uint32_t kadd = ks * 32;   // 16 elems * 2B
                uint32_t afr[4][4], bfr[2][4];
#pragma unroll
                for (int mt = 0; mt < 4; mt++) ldsm_x4(ua + aoff[mt] + kadd, afr[mt]);
#pragma unroll
                for (int nt2 = 0; nt2 < 2; nt2++) ldsm_x4(ub + boff[nt2] + kadd, bfr[nt2]);
#pragma unroll
                for (int mt = 0; mt < 4; mt++)
#pragma unroll
                    for (int nt = 0; nt < 4; nt++)
                        mma_bf16(acc[mt][nt], afr[mt], bfr[nt >> 1] + (nt & 1) * 2);
            }
        }
    }

    // epilogue
    const int erow = lane >> 2;
    const int ecol = (lane & 3) * 2;
#pragma unroll
    for (int mt = 0; mt < 4; mt++) {
#pragma unroll
        for (int nt = 0; nt < 4; nt++) {
            float* Cr = C + (size_t)(bm * 128 + warp_m + mt * 16 + erow) * N
                          + bn * 128 + warp_n + nt * 8 + ecol;
            *(float2*)Cr           = make_float2(acc[mt][nt][0], acc[mt][nt][1]);
            *(float2*)(Cr + 8 * (size_t)N) = make_float2(acc[mt][nt][2], acc[mt][nt][3]);
        }
    }
}

// ---------------------------------------------------------------------------
// RoPE (interleaved pairs), unchanged.
// ---------------------------------------------------------------------------
__global__ void rope_kernel(float* __restrict__ x,
                            const float* __restrict__ cs,
                            const float* __restrict__ sn,
                            int nh, int total_pairs)
{
    int p = blockIdx.x * blockDim.x + threadIdx.x;
    if (p >= total_pairs) return;
    int d2 = p & 31;
    int s  = (p / (32 * nh)) & (S_ - 1);
    float c  = cs[s * 32 + d2];
    float si = sn[s * 32 + d2];
    float2 xv = *(float2*)(x + (size_t)p * 2);
    float2 r;
    r.x = xv.x * c - xv.y * si;
    r.y = xv.x * si + xv.y * c;
    *(float2*)(x + (size_t)p * 2) = r;
}

// ---------------------------------------------------------------------------
// Flash attention with block-causal mask (block size 8), GQA rep=2. Unchanged.
// ---------------------------------------------------------------------------
__global__ __launch_bounds__(128) void attn_kernel(const float* __restrict__ q,
                                                   const float* __restrict__ k,
                                                   const float* __restrict__ v,
                                                   float* __restrict__ out)
{
    const int qt  = blockIdx.x;
    const int h   = blockIdx.y;
    const int b   = blockIdx.z;
    const int kvh = h >> 1;
    const int tid = threadIdx.x;
    const int i   = qt * 128 + tid;
    const int qblk = i >> 3;

    __shared__ float ks[32][64];
    __shared__ float vs[32][64];

    float qr[64];
    const float* qptr = q + (((size_t)(b * S_ + i) * NH_) + h) * HD_;
#pragma unroll
    for (int d = 0; d < 64; d += 4) {
        float4 t = *(const float4*)(qptr + d);
        qr[d] = t.x; qr[d+1] = t.y; qr[d+2] = t.z; qr[d+3] = t.w;
    }

    float m = -1e30f, l = 0.f;
    float acc[64];
#pragma unroll
    for (int d = 0; d < 64; d++) acc[d] = 0.f;

    const int ntiles = 4 * qt + 4;
    for (int kt = 0; kt < ntiles; kt++) {
        const float* kbase = k + (((size_t)(b * S_ + kt * 32) * NKV_) + kvh) * HD_;
        const float* vbase = v + (((size_t)(b * S_ + kt * 32) * NKV_) + kvh) * HD_;
#pragma unroll
        for (int idx = tid; idx < 32 * 16; idx += 128) {
            int row = idx >> 4;
            int c4  = (idx & 15) * 4;
            *(float4*)&ks[row][c4] = *(const float4*)(kbase + (size_t)row * (NKV_ * HD_) + c4);
            *(float4*)&vs[row][c4] = *(const float4*)(vbase + (size_t)row * (NKV_ * HD_) + c4);
        }
        __syncthreads();

        const bool diag = (kt >= 4 * qt);
        float s[32];
        float tmax = -1e30f;
#pragma unroll
        for (int j = 0; j < 32; j++) {
            float sc = 0.f;
#pragma unroll
            for (int d = 0; d < 64; d++) sc = fmaf(qr[d], ks[j][d], sc);
            sc *= 0.125f;
            if (diag) {
                int jg = kt * 32 + j;
                if ((jg >> 3) > qblk) sc = -1e30f;
            }
            s[j] = sc;
            tmax = fmaxf(tmax, sc);
        }

        float mnew  = fmaxf(m, tmax);
        float alpha = __expf(m - mnew);
        l *= alpha;
#pragma unroll
        for (int d = 0; d < 64; d++) acc[d] *= alpha;
#pragma unroll
        for (int j = 0; j < 32; j++) {
            float p = __expf(s[j] - mnew);
            l += p;
#pragma unroll
            for (int d = 0; d < 64; d++) acc[d] = fmaf(p, vs[j][d], acc[d]);
        }
        m = mnew;
        __syncthreads();
    }

    const float inv = 1.f / l;
    float* optr = out + (((size_t)(b * S_ + i) * NH_) + h) * HD_;
#pragma unroll
    for (int d = 0; d < 64; d += 4) {
        float4 o = {acc[d] * inv, acc[d+1] * inv, acc[d+2] * inv, acc[d+3] * inv};
        *(float4*)(optr + d) = o;
    }
}

// ---------------------------------------------------------------------------
extern "C" void kernel_launch(void* const* d_in, const int* in_sizes, int n_in,
                              void* d_out, int out_size)
{
    const float* x   = (const float*)d_in[0];
    const float* wq  = (const float*)d_in[1];
    const float* wk  = (const float*)d_in[2];
    const float* wv  = (const float*)d_in[3];
    const float* wo  = (const float*)d_in[4];
    const float* fcc = (const float*)d_in[5];
    const float* fcs = (const float*)d_in[6];
    (void)in_sizes; (void)n_in;

    float *q, *k, *v, *ao;
    cudaGetSymbolAddress((void**)&q,  g_q);
    cudaGetSymbolAddress((void**)&k,  g_k);
    cudaGetSymbolAddress((void**)&v,  g_v);
    cudaGetSymbolAddress((void**)&ao, g_ao);

    const int M = B_ * S_;   // 8192

    // QKV projections (HMMA bf16 hi/lo split)
    hgemm<<<dim3(NH_*HD_/128,  M/128), 256>>>(x, wq, q, NH_*HD_,  D_);
    hgemm<<<dim3(NKV_*HD_/128, M/128), 256>>>(x, wk, k, NKV_*HD_, D_);
    hgemm<<<dim3(NKV_*HD_/128, M/128), 256>>>(x, wv, v, NKV_*HD_, D_);

    // RoPE on q and k
    {
        int qp = B_ * S_ * NH_ * (HD_ / 2);
        int kp = B_ * S_ * NKV_ * (HD_ / 2);
        rope_kernel<<<(qp + 255) / 256, 256>>>(q, fcc, fcs, NH_, qp);
        rope_kernel<<<(kp + 255) / 256, 256>>>(k, fcc, fcs, NKV_, kp);
    }

    // Attention
    attn_kernel<<<dim3(S_/128, NH_, B_), 128>>>(q, k, v, ao);

    // Output projection -> d_out (HMMA)
    hgemm<<<dim3(D_/128, M/128), 256>>>(ao, wo, (float*)d_out, D_, D_);
    (void)out_size;
}

// round 10
// speedup vs baseline: 1.4478x; 1.1787x over previous
#include <cuda_runtime.h>
#include <cuda_bf16.h>
#include <math.h>
#include <stdint.h>

#define B_ 8
#define S_ 1024
#define D_ 1024
#define NH_ 16
#define NKV_ 8
#define HD_ 64

// Scratch (allocation-free rule: __device__ globals)
__device__ float g_q[B_*S_*NH_*HD_];    // 32 MB
__device__ float g_k[B_*S_*NKV_*HD_];   // 16 MB
__device__ float g_v[B_*S_*NKV_*HD_];   // 16 MB
__device__ float g_ao[B_*S_*NH_*HD_];   // 32 MB

// ---------------------------------------------------------------------------
// helpers
// ---------------------------------------------------------------------------
__device__ __forceinline__ uint32_t smem_u32(const void* p) {
    uint32_t a;
    asm("{ .reg .u64 t; cvta.to.shared.u64 t, %1; cvt.u32.u64 %0, t; }" : "=r"(a) : "l"(p));
    return a;
}

__device__ __forceinline__ void ldsm_x4(uint32_t addr, uint32_t* d) {
    asm volatile("ldmatrix.sync.aligned.m8n8.x4.shared.b16 {%0,%1,%2,%3}, [%4];"
                 : "=r"(d[0]), "=r"(d[1]), "=r"(d[2]), "=r"(d[3]) : "r"(addr));
}
__device__ __forceinline__ void ldsm_x4_t(uint32_t addr, uint32_t* d) {
    asm volatile("ldmatrix.sync.aligned.m8n8.x4.trans.shared.b16 {%0,%1,%2,%3}, [%4];"
                 : "=r"(d[0]), "=r"(d[1]), "=r"(d[2]), "=r"(d[3]) : "r"(addr));
}

__device__ __forceinline__ void mma_bf16(float* c, const uint32_t* a, const uint32_t* b) {
    asm volatile(
        "mma.sync.aligned.m16n8k16.row.col.f32.bf16.bf16.f32 "
        "{%0,%1,%2,%3}, {%4,%5,%6,%7}, {%8,%9}, {%0,%1,%2,%3};"
        : "+f"(c[0]), "+f"(c[1]), "+f"(c[2]), "+f"(c[3])
        : "r"(a[0]), "r"(a[1]), "r"(a[2]), "r"(a[3]), "r"(b[0]), "r"(b[1]));
}

__device__ __forceinline__ uint32_t pk_bf2(float lo, float hi) {
    __nv_bfloat162 t;
    t.x = __float2bfloat16(lo);
    t.y = __float2bfloat16(hi);
    return *reinterpret_cast<uint32_t*>(&t);
}
__device__ __forceinline__ float bf_hi(float x, float* rem) {
    __nv_bfloat16 h = __float2bfloat16(x);
    float hf = __bfloat162float(h);
    *rem = x - hf;
    return hf;
}

// ---------------------------------------------------------------------------
// HMMA GEMM (unchanged from R8-passing version).
// ---------------------------------------------------------------------------
#define LDPAD 40

__global__ __launch_bounds__(256, 1) void hgemm(const float* __restrict__ A,
                                                const float* __restrict__ W,
                                                float* __restrict__ C,
                                                int N, int K)
{
    __shared__ __align__(16) __nv_bfloat16 sAh[128][LDPAD];
    __shared__ __align__(16) __nv_bfloat16 sAl[128][LDPAD];
    __shared__ __align__(16) __nv_bfloat16 sBh[128][LDPAD];
    __shared__ __align__(16) __nv_bfloat16 sBl[128][LDPAD];

    const int tid = threadIdx.x, lane = tid & 31, wid = tid >> 5;
    const int bn = blockIdx.x, bm = blockIdx.y;
    const int warp_m = (wid & 1) * 64;
    const int warp_n = (wid >> 1) * 32;

    const int arow = tid >> 1;
    const int ahalf = tid & 1;
    const float* Ap = A + (size_t)(bm * 128 + arow) * K + ahalf * 16;
    const int bnrow = tid & 127;
    const int kg = (tid >> 7) * 16;
    const float* Wp = W + (size_t)bn * 128 + bnrow;

    const int g = lane >> 3, r = lane & 7;
    const uint32_t uAh = smem_u32(sAh), uAl = smem_u32(sAl);
    const uint32_t uBh = smem_u32(sBh), uBl = smem_u32(sBl);
    uint32_t aoff[4], boff[2];
#pragma unroll
    for (int mt = 0; mt < 4; mt++)
        aoff[mt] = ((warp_m + mt * 16 + (g & 1) * 8 + r) * LDPAD + (g >> 1) * 8) * 2;
#pragma unroll
    for (int nt2 = 0; nt2 < 2; nt2++)
        boff[nt2] = ((warp_n + nt2 * 16 + (g >> 1) * 8 + r) * LDPAD + (g & 1) * 8) * 2;

    float acc[4][4][4];
#pragma unroll
    for (int i = 0; i < 4; i++)
#pragma unroll
        for (int j = 0; j < 4; j++)
#pragma unroll
            for (int t = 0; t < 4; t++) acc[i][j][t] = 0.f;

    const int NCH = K / 32;
    for (int ch = 0; ch < NCH; ch++) {
        const int k0g = ch * 32;

        float4 av[4];
#pragma unroll
        for (int i = 0; i < 4; i++)
            av[i] = *(const float4*)(Ap + k0g + i * 4);
        float bv[16];
#pragma unroll
        for (int j = 0; j < 16; j++)
            bv[j] = Wp[(size_t)(k0g + kg + j) * N];

        __syncthreads();

#pragma unroll
        for (int i = 0; i < 4; i++) {
            float r0, r1, r2, r3;
            float h0 = bf_hi(av[i].x, &r0), h1 = bf_hi(av[i].y, &r1);
            float h2 = bf_hi(av[i].z, &r2), h3 = bf_hi(av[i].w, &r3);
            int c0 = ahalf * 16 + i * 4;
            *(uint2*)&sAh[arow][c0] = make_uint2(pk_bf2(h0, h1), pk_bf2(h2, h3));
            *(uint2*)&sAl[arow][c0] = make_uint2(pk_bf2(r0, r1), pk_bf2(r2, r3));
        }
#pragma unroll
        for (int jb = 0; jb < 4; jb++) {
            float r0, r1, r2, r3;
            float h0 = bf_hi(bv[jb*4+0], &r0), h1 = bf_hi(bv[jb*4+1], &r1);
            float h2 = bf_hi(bv[jb*4+2], &r2), h3 = bf_hi(bv[jb*4+3], &r3);
            int c0 = kg + jb * 4;
            *(uint2*)&sBh[bnrow][c0] = make_uint2(pk_bf2(h0, h1), pk_bf2(h2, h3));
            *(uint2*)&sBl[bnrow][c0] = make_uint2(pk_bf2(r0, r1), pk_bf2(r2, r3));
        }
        __syncthreads();

#pragma unroll
        for (int p = 0; p < 3; p++) {
            const uint32_t ua = (p == 2) ? uAl : uAh;
            const uint32_t ub = (p == 1) ? uBl : uBh;
#pragma unroll
            for (int ks = 0; ks < 2; ks++) {
                const uint32_t kadd = ks * 32;
                uint32_t afr[4][4], bfr[2][4];
#pragma unroll
                for (int mt = 0; mt < 4; mt++) ldsm_x4(ua + aoff[mt] + kadd, afr[mt]);
#pragma unroll
                for (int nt2 = 0; nt2 < 2; nt2++) ldsm_x4(ub + boff[nt2] + kadd, bfr[nt2]);
#pragma unroll
                for (int mt = 0; mt < 4; mt++)
#pragma unroll
                    for (int nt = 0; nt < 4; nt++)
                        mma_bf16(acc[mt][nt], afr[mt], bfr[nt >> 1] + (nt & 1) * 2);
            }
        }
    }

    const int erow = lane >> 2;
    const int ecol = (lane & 3) * 2;
#pragma unroll
    for (int mt = 0; mt < 4; mt++) {
#pragma unroll
        for (int nt = 0; nt < 4; nt++) {
            float* Cr = C + (size_t)(bm * 128 + warp_m + mt * 16 + erow) * N
                          + bn * 128 + warp_n + nt * 8 + ecol;
            *(float2*)Cr           = make_float2(acc[mt][nt][0], acc[mt][nt][1]);
            *(float2*)(Cr + 8 * (size_t)N) = make_float2(acc[mt][nt][2], acc[mt][nt][3]);
        }
    }
}

// ---------------------------------------------------------------------------
// RoPE (unchanged)
// ---------------------------------------------------------------------------
__global__ void rope_kernel(float* __restrict__ x,
                            const float* __restrict__ cs,
                            const float* __restrict__ sn,
                            int nh, int total_pairs)
{
    int p = blockIdx.x * blockDim.x + threadIdx.x;
    if (p >= total_pairs) return;
    int d2 = p & 31;
    int s  = (p / (32 * nh)) & (S_ - 1);
    float c  = cs[s * 32 + d2];
    float si = sn[s * 32 + d2];
    float2 xv = *(float2*)(x + (size_t)p * 2);
    float2 r;
    r.x = xv.x * c - xv.y * si;
    r.y = xv.x * si + xv.y * c;
    *(float2*)(x + (size_t)p * 2) = r;
}

// ---------------------------------------------------------------------------
// HMMA flash attention, block-causal (blk 8), GQA rep 2, hi/lo bf16 split.
// CTA: 256 thr (8 warps), q-tile 128 (warp = m16), k-tile 64.
// smem: 4 tiles of [64][72] bf16 (Kh,Kl,Vh,Vl); Q phase reuses same memory
// as 2 tiles of [128][72] (Qh,Ql).  pad 72 -> 144B rows, conflict-free ldsm.
// ---------------------------------------------------------------------------
#define APAD 72
#define TILE_E (64 * APAD)      // elems per 64-row tile

__global__ __launch_bounds__(256) void attn_mma(const float* __restrict__ q,
                                                const float* __restrict__ k,
                                                const float* __restrict__ v,
                                                float* __restrict__ out)
{
    __shared__ __align__(16) __nv_bfloat16 sm[4 * TILE_E];

    const int tid = threadIdx.x, lane = tid & 31, wid = tid >> 5;
    const int qt = blockIdx.x, h = blockIdx.y, b = blockIdx.z;
    const int kvh = h >> 1;
    const int lg = lane >> 3, lr = lane & 7;
    const int quad = lane >> 2, qd = lane & 3;

    const uint32_t uS = smem_u32(sm);

    // ---- Q stage: load, scale by 1/8, hi/lo split into smem ----
    {
        const int row = tid >> 1, half = tid & 1;
        const float* gq = q + (((size_t)(b * S_ + qt * 128 + row)) * NH_ + h) * HD_ + half * 32;
        __nv_bfloat16* dh = sm + row * APAD + half * 32;
        __nv_bfloat16* dl = sm + 2 * TILE_E + row * APAD + half * 32;
#pragma unroll
        for (int i = 0; i < 8; i++) {
            float4 f = *(const float4*)(gq + i * 4);
            f.x *= 0.125f; f.y *= 0.125f; f.z *= 0.125f; f.w *= 0.125f;
            float r0, r1, r2, r3;
            float h0 = bf_hi(f.x, &r0), h1 = bf_hi(f.y, &r1);
            float h2 = bf_hi(f.z, &r2), h3 = bf_hi(f.w, &r3);
            *(uint2*)(dh + i * 4) = make_uint2(pk_bf2(h0, h1), pk_bf2(h2, h3));
            *(uint2*)(dl + i * 4) = make_uint2(pk_bf2(r0, r1), pk_bf2(r2, r3));
        }
    }
    __syncthreads();

    // ---- Q fragments (held for whole kernel) ----
    uint32_t qh[4][4], ql[4][4];
    {
        const int rowa = wid * 16 + (lg & 1) * 8 + lr;
#pragma unroll
        for (int kc = 0; kc < 4; kc++) {
            const uint32_t off = (uint32_t)(rowa * APAD + (lg >> 1) * 8 + kc * 16) * 2;
            ldsm_x4(uS + off, qh[kc]);
            ldsm_x4(uS + 2 * TILE_E * 2 + off, ql[kc]);
        }
    }

    const uint32_t uKh = uS;
    const uint32_t uKl = uS + TILE_E * 2;
    const uint32_t uVh = uS + 2 * TILE_E * 2;
    const uint32_t uVl = uS + 3 * TILE_E * 2;

    float o[8][4];
#pragma unroll
    for (int t = 0; t < 8; t++)
#pragma unroll
        for (int j = 0; j < 4; j++) o[t][j] = 0.f;
    float m0 = -1e30f, m1 = -1e30f, l0 = 0.f, l1 = 0.f;

    const int qbaseG = qt * 128 + wid * 16;
    const int lim0 = (qbaseG + quad) | 7;
    const int lim1 = (qbaseG + quad + 8) | 7;
    const int ntiles = 2 * qt + 2;

    const int krow = tid >> 2, kc4 = (tid & 3) * 16;
    __nv_bfloat16* skh = sm + krow * APAD + kc4;
    __nv_bfloat16* skl = skh + TILE_E;
    __nv_bfloat16* svh = skh + 2 * TILE_E;
    __nv_bfloat16* svl = skh + 3 * TILE_E;

    for (int kt = 0; kt < ntiles; kt++) {
        // gmem stage (overlaps previous tile's compute)
        const float* kb = k + (((size_t)(b * S_ + kt * 64 + krow)) * NKV_ + kvh) * HD_ + kc4;
        const float* vb = v + (((size_t)(b * S_ + kt * 64 + krow)) * NKV_ + kvh) * HD_ + kc4;
        float4 kr[4], vr[4];
#pragma unroll
        for (int i = 0; i < 4; i++) { kr[i] = *(const float4*)(kb + i * 4); }
#pragma unroll
        for (int i = 0; i < 4; i++) { vr[i] = *(const float4*)(vb + i * 4); }

        __syncthreads();   // previous tile's consumers done

#pragma unroll
        for (int i = 0; i < 4; i++) {
            float r0, r1, r2, r3;
            float h0 = bf_hi(kr[i].x, &r0), h1 = bf_hi(kr[i].y, &r1);
            float h2 = bf_hi(kr[i].z, &r2), h3 = bf_hi(kr[i].w, &r3);
            *(uint2*)(skh + i * 4) = make_uint2(pk_bf2(h0, h1), pk_bf2(h2, h3));
            *(uint2*)(skl + i * 4) = make_uint2(pk_bf2(r0, r1), pk_bf2(r2, r3));
            h0 = bf_hi(vr[i].x, &r0); h1 = bf_hi(vr[i].y, &r1);
            h2 = bf_hi(vr[i].z, &r2); h3 = bf_hi(vr[i].w, &r3);
            *(uint2*)(svh + i * 4) = make_uint2(pk_bf2(h0, h1), pk_bf2(h2, h3));
            *(uint2*)(svl + i * 4) = make_uint2(pk_bf2(r0, r1), pk_bf2(r2, r3));
        }
        __syncthreads();

        if (kt * 64 > qbaseG + 15) continue;   // warp fully above diagonal

        // ---- S = Q @ K^T (hi*hi + lo*hi with K hi, then hi*lo) ----
        float s[8][4];
#pragma unroll
        for (int t = 0; t < 8; t++)
#pragma unroll
            for (int j = 0; j < 4; j++) s[t][j] = 0.f;

#pragma unroll
        for (int kc = 0; kc < 4; kc++) {
#pragma unroll
            for (int nt2 = 0; nt2 < 4; nt2++) {
                const uint32_t boff =
                    (uint32_t)((nt2 * 16 + (lg >> 1) * 8 + lr) * APAD + (lg & 1) * 8 + kc * 16) * 2;
                uint32_t f[4];
                ldsm_x4(uKh + boff, f);
                mma_bf16(s[nt2 * 2],     qh[kc], f);
                mma_bf16(s[nt2 * 2 + 1], qh[kc], f + 2);
                mma_bf16(s[nt2 * 2],     ql[kc], f);
                mma_bf16(s[nt2 * 2 + 1], ql[kc], f + 2);
            }
#pragma unroll
            for (int nt2 = 0; nt2 < 4; nt2++) {
                const uint32_t boff =
                    (uint32_t)((nt2 * 16 + (lg >> 1) * 8 + lr) * APAD + (lg & 1) * 8 + kc * 16) * 2;
                uint32_t f[4];
                ldsm_x4(uKl + boff, f);
                mma_bf16(s[nt2 * 2],     qh[kc], f);
                mma_bf16(s[nt2 * 2 + 1], qh[kc], f + 2);
            }
        }

        // ---- mask (any tile whose last key exceeds the SMALLEST row limit) ----
        if (kt * 64 + 63 > qbaseG + 7) {
#pragma unroll
            for (int t = 0; t < 8; t++) {
                const int key = kt * 64 + t * 8 + qd * 2;
                if (key     > lim0) s[t][0] = -1e30f;
                if (key + 1 > lim0) s[t][1] = -1e30f;
                if (key     > lim1) s[t][2] = -1e30f;
                if (key + 1 > lim1) s[t][3] = -1e30f;
            }
        }

        // ---- online softmax ----
        float mx0 = -1e30f, mx1 = -1e30f;
#pragma unroll
        for (int t = 0; t < 8; t++) {
            mx0 = fmaxf(mx0, fmaxf(s[t][0], s[t][1]));
            mx1 = fmaxf(mx1, fmaxf(s[t][2], s[t][3]));
        }
        mx0 = fmaxf(mx0, __shfl_xor_sync(0xffffffffu, mx0, 1));
        mx0 = fmaxf(mx0, __shfl_xor_sync(0xffffffffu, mx0, 2));
        mx1 = fmaxf(mx1, __shfl_xor_sync(0xffffffffu, mx1, 1));
        mx1 = fmaxf(mx1, __shfl_xor_sync(0xffffffffu, mx1, 2));

        const float mn0 = fmaxf(m0, mx0), mn1 = fmaxf(m1, mx1);
        const float a0 = __expf(m0 - mn0), a1 = __expf(m1 - mn1);
        l0 *= a0; l1 *= a1;
#pragma unroll
        for (int t = 0; t < 8; t++) {
            o[t][0] *= a0; o[t][1] *= a0; o[t][2] *= a1; o[t][3] *= a1;
        }
        float sl0 = 0.f, sl1 = 0.f;
#pragma unroll
        for (int t = 0; t < 8; t++) {
            s[t][0] = __expf(s[t][0] - mn0); s[t][1] = __expf(s[t][1] - mn0);
            s[t][2] = __expf(s[t][2] - mn1); s[t][3] = __expf(s[t][3] - mn1);
            sl0 += s[t][0] + s[t][1];
            sl1 += s[t][2] + s[t][3];
        }
        sl0 += __shfl_xor_sync(0xffffffffu, sl0, 1);
        sl0 += __shfl_xor_sync(0xffffffffu, sl0, 2);
        sl1 += __shfl_xor_sync(0xffffffffu, sl1, 1);
        sl1 += __shfl_xor_sync(0xffffffffu, sl1, 2);
        l0 += sl0; l1 += sl1;
        m0 = mn0; m1 = mn1;

        // ---- pack P hi/lo as A-fragments ----
        uint32_t ph[8][2], pl[8][2];
#pragma unroll
        for (int t = 0; t < 8; t++) {
            float r0, r1, r2, r3;
            float h0 = bf_hi(s[t][0], &r0), h1 = bf_hi(s[t][1], &r1);
            float h2 = bf_hi(s[t][2], &r2), h3 = bf_hi(s[t][3], &r3);
            ph[t][0] = pk_bf2(h0, h1); ph[t][1] = pk_bf2(h2, h3);
            pl[t][0] = pk_bf2(r0, r1); pl[t][1] = pk_bf2(r2, r3);
        }

        // ---- O += P @ V ----
#pragma unroll
        for (int kc = 0; kc < 4; kc++) {
            uint32_t ah[4] = {ph[2*kc][0], ph[2*kc][1], ph[2*kc+1][0], ph[2*kc+1][1]};
            uint32_t al[4] = {pl[2*kc][0], pl[2*kc][1], pl[2*kc+1][0], pl[2*kc+1][1]};
#pragma unroll
            for (int nt2 = 0; nt2 < 4; nt2++) {
                const uint32_t voff =
                    (uint32_t)((kc * 16 + (lg & 1) * 8 + lr) * APAD + nt2 * 16 + (lg >> 1) * 8) * 2;
                uint32_t f[4];
                ldsm_x4_t(uVh + voff, f);
                mma_bf16(o[nt2 * 2],     ah, f);
                mma_bf16(o[nt2 * 2 + 1], ah, f + 2);
                mma_bf16(o[nt2 * 2],     al, f);
                mma_bf16(o[nt2 * 2 + 1], al, f + 2);
            }
#pragma unroll
            for (int nt2 = 0; nt2 < 4; nt2++) {
                const uint32_t voff =
                    (uint32_t)((kc * 16 + (lg & 1) * 8 + lr) * APAD + nt2 * 16 + (lg >> 1) * 8) * 2;
                uint32_t f[4];
                ldsm_x4_t(uVl + voff, f);
                mma_bf16(o[nt2 * 2],     ah, f);
                mma_bf16(o[nt2 * 2 + 1], ah, f + 2);
            }
        }
    }

    // ---- epilogue ----
    const float inv0 = 1.f / l0, inv1 = 1.f / l1;
    const int row0 = qbaseG + quad;
    float* o0 = out + (((size_t)(b * S_ + row0)) * NH_ + h) * HD_ + qd * 2;
    float* o1 = out + (((size_t)(b * S_ + row0 + 8)) * NH_ + h) * HD_ + qd * 2;
#pragma unroll
    for (int t = 0; t < 8; t++) {
        *(float2*)(o0 + t * 8) = make_float2(o[t][0] * inv0, o[t][1] * inv0);
        *(float2*)(o1 + t * 8) = make_float2(o[t][2] * inv1, o[t][3] * inv1);
    }
}

// ---------------------------------------------------------------------------
extern "C" void kernel_launch(void* const* d_in, const int* in_sizes, int n_in,
                              void* d_out, int out_size)
{
    const float* x   = (const float*)d_in[0];
    const float* wq  = (const float*)d_in[1];
    const float* wk  = (const float*)d_in[2];
    const float* wv  = (const float*)d_in[3];
    const float* wo  = (const float*)d_in[4];
    const float* fcc = (const float*)d_in[5];
    const float* fcs = (const float*)d_in[6];
    (void)in_sizes; (void)n_in;

    float *q, *k, *v, *ao;
    cudaGetSymbolAddress((void**)&q,  g_q);
    cudaGetSymbolAddress((void**)&k,  g_k);
    cudaGetSymbolAddress((void**)&v,  g_v);
    cudaGetSymbolAddress((void**)&ao, g_ao);

    const int M = B_ * S_;   // 8192

    // QKV projections (HMMA bf16 hi/lo split)
    hgemm<<<dim3(NH_*HD_/128,  M/128), 256>>>(x, wq, q, NH_*HD_,  D_);
    hgemm<<<dim3(NKV_*HD_/128, M/128), 256>>>(x, wk, k, NKV_*HD_, D_);
    hgemm<<<dim3(NKV_*HD_/128, M/128), 256>>>(x, wv, v, NKV_*HD_, D_);

    // RoPE on q and k
    {
        int qp = B_ * S_ * NH_ * (HD_ / 2);
        int kp = B_ * S_ * NKV_ * (HD_ / 2);
        rope_kernel<<<(qp + 255) / 256, 256>>>(q, fcc, fcs, NH_, qp);
        rope_kernel<<<(kp + 255) / 256, 256>>>(k, fcc, fcs, NKV_, kp);
    }

    // Attention (HMMA flash, hi/lo split)
    attn_mma<<<dim3(S_/128, NH_, B_), 256>>>(q, k, v, ao);

    // Output projection -> d_out (HMMA)
    hgemm<<<dim3(D_/128, M/128), 256>>>(ao, wo, (float*)d_out, D_, D_);
    (void)out_size;
}

// round 11
// speedup vs baseline: 1.7138x; 1.1837x over previous
#include <cuda_runtime.h>
#include <cuda_bf16.h>
#include <math.h>
#include <stdint.h>

#define B_ 8
#define S_ 1024
#define D_ 1024
#define NH_ 16
#define NKV_ 8
#define HD_ 64
#define M_ (B_*S_)

// ---------------------------------------------------------------------------
// Scratch (allocation-free rule: __device__ globals)
// ---------------------------------------------------------------------------
__device__ float g_q[M_*NH_*HD_];            // fp32 q (pre-rope)
__device__ float g_k[M_*NKV_*HD_];           // fp32 k (pre-rope)
__device__ float g_v[M_*NKV_*HD_];           // fp32 v

__device__ __nv_bfloat16 g_xh[M_*D_],  g_xl[M_*D_];          // x split
__device__ __nv_bfloat16 g_wqh[D_*D_], g_wql[D_*D_];         // wq^T split [N][K]
__device__ __nv_bfloat16 g_wkh[(D_/2)*D_], g_wkl[(D_/2)*D_]; // wk^T
__device__ __nv_bfloat16 g_wvh[(D_/2)*D_], g_wvl[(D_/2)*D_]; // wv^T
__device__ __nv_bfloat16 g_woh[D_*D_], g_wol[D_*D_];         // wo^T
__device__ __nv_bfloat16 g_qh[M_*NH_*HD_],  g_ql[M_*NH_*HD_];   // roped, x0.125
__device__ __nv_bfloat16 g_kh[M_*NKV_*HD_], g_kl[M_*NKV_*HD_];  // roped
__device__ __nv_bfloat16 g_vh[M_*NKV_*HD_], g_vl[M_*NKV_*HD_];
__device__ __nv_bfloat16 g_aoh[M_*NH_*HD_], g_aol[M_*NH_*HD_];  // attn out split

// ---------------------------------------------------------------------------
// helpers
// ---------------------------------------------------------------------------
__device__ __forceinline__ uint32_t smem_u32(const void* p) {
    uint32_t a;
    asm("{ .reg .u64 t; cvta.to.shared.u64 t, %1; cvt.u32.u64 %0, t; }" : "=r"(a) : "l"(p));
    return a;
}
__device__ __forceinline__ void ldsm_x4(uint32_t addr, uint32_t* d) {
    asm volatile("ldmatrix.sync.aligned.m8n8.x4.shared.b16 {%0,%1,%2,%3}, [%4];"
                 : "=r"(d[0]), "=r"(d[1]), "=r"(d[2]), "=r"(d[3]) : "r"(addr));
}
__device__ __forceinline__ void ldsm_x4_t(uint32_t addr, uint32_t* d) {
    asm volatile("ldmatrix.sync.aligned.m8n8.x4.trans.shared.b16 {%0,%1,%2,%3}, [%4];"
                 : "=r"(d[0]), "=r"(d[1]), "=r"(d[2]), "=r"(d[3]) : "r"(addr));
}
__device__ __forceinline__ void mma_bf16(float* c, const uint32_t* a, const uint32_t* b) {
    asm volatile(
        "mma.sync.aligned.m16n8k16.row.col.f32.bf16.bf16.f32 "
        "{%0,%1,%2,%3}, {%4,%5,%6,%7}, {%8,%9}, {%0,%1,%2,%3};"
        : "+f"(c[0]), "+f"(c[1]), "+f"(c[2]), "+f"(c[3])
        : "r"(a[0]), "r"(a[1]), "r"(a[2]), "r"(a[3]), "r"(b[0]), "r"(b[1]));
}
__device__ __forceinline__ uint32_t pk_bf2(float lo, float hi) {
    __nv_bfloat162 t;
    t.x = __float2bfloat16(lo);
    t.y = __float2bfloat16(hi);
    return *reinterpret_cast<uint32_t*>(&t);
}
__device__ __forceinline__ float bf_hi(float x, float* rem) {
    __nv_bfloat16 h = __float2bfloat16(x);
    float hf = __bfloat162float(h);
    *rem = x - hf;
    return hf;
}

// ---------------------------------------------------------------------------
// elementwise split: fp32 -> (hi, lo) bf16.  n4 = count/4.
// ---------------------------------------------------------------------------
__global__ void split_f32(const float* __restrict__ src,
                          __nv_bfloat16* __restrict__ dh,
                          __nv_bfloat16* __restrict__ dl, int n4)
{
    int i = blockIdx.x * blockDim.x + threadIdx.x;
    if (i >= n4) return;
    float4 f = *(const float4*)(src + (size_t)i * 4);
    float r0, r1, r2, r3;
    float h0 = bf_hi(f.x, &r0), h1 = bf_hi(f.y, &r1);
    float h2 = bf_hi(f.z, &r2), h3 = bf_hi(f.w, &r3);
    *(uint2*)(dh + (size_t)i * 4) = make_uint2(pk_bf2(h0, h1), pk_bf2(h2, h3));
    *(uint2*)(dl + (size_t)i * 4) = make_uint2(pk_bf2(r0, r1), pk_bf2(r2, r3));
}

// ---------------------------------------------------------------------------
// transpose + split: W[K,N] fp32 -> T[N,K] hi/lo bf16.  grid (N/32, K/32), blk (32,8)
// ---------------------------------------------------------------------------
__global__ void trans_split(const float* __restrict__ W,
                            __nv_bfloat16* __restrict__ Th,
                            __nv_bfloat16* __restrict__ Tl, int N, int K)
{
    __shared__ float t[32][33];
    const int n0 = blockIdx.x * 32, k0 = blockIdx.y * 32;
    const int tx = threadIdx.x, ty = threadIdx.y;
#pragma unroll
    for (int i = 0; i < 4; i++)
        t[ty + i * 8][tx] = W[(size_t)(k0 + ty + i * 8) * N + n0 + tx];
    __syncthreads();
#pragma unroll
    for (int i = 0; i < 4; i++) {
        float x = t[tx][ty + i * 8];
        float r;
        float h = bf_hi(x, &r);
        size_t o = (size_t)(n0 + ty + i * 8) * K + k0 + tx;
        Th[o] = __float2bfloat16(h);
        Tl[o] = __float2bfloat16(r);
    }
}

// ---------------------------------------------------------------------------
// HMMA GEMM on pre-split bf16: C[M,N] = (Ah+Al)[M,K] @ (Bh+Bl)^T[N,K]
// 3 passes AhBh + AhBl + AlBh.  Tile 128x128, BK=32, 256 thr, 8 warps 2m x 4n.
// ---------------------------------------------------------------------------
#define LDPAD 40

__global__ __launch_bounds__(256, 2) void hgemm_s(const __nv_bfloat16* __restrict__ Ah,
                                                  const __nv_bfloat16* __restrict__ Al,
                                                  const __nv_bfloat16* __restrict__ Bh,
                                                  const __nv_bfloat16* __restrict__ Bl,
                                                  float* __restrict__ C,
                                                  int N, int K)
{
    __shared__ __align__(16) __nv_bfloat16 sAh[128][LDPAD];
    __shared__ __align__(16) __nv_bfloat16 sAl[128][LDPAD];
    __shared__ __align__(16) __nv_bfloat16 sBh[128][LDPAD];
    __shared__ __align__(16) __nv_bfloat16 sBl[128][LDPAD];

    const int tid = threadIdx.x, lane = tid & 31, wid = tid >> 5;
    const int bn = blockIdx.x, bm = blockIdx.y;
    const int warp_m = (wid & 1) * 64;
    const int warp_n = (wid >> 1) * 32;

    const int row  = tid >> 1;          // 0..127 (for both A and B tiles)
    const int half = tid & 1;           // 16-element halves
    const __nv_bfloat16* pAh = Ah + (size_t)(bm * 128 + row) * K + half * 16;
    const __nv_bfloat16* pAl = Al + (size_t)(bm * 128 + row) * K + half * 16;
    const __nv_bfloat16* pBh = Bh + (size_t)(bn * 128 + row) * K + half * 16;
    const __nv_bfloat16* pBl = Bl + (size_t)(bn * 128 + row) * K + half * 16;

    const int g = lane >> 3, r = lane & 7;
    const uint32_t uAh = smem_u32(sAh), uAl = smem_u32(sAl);
    const uint32_t uBh = smem_u32(sBh), uBl = smem_u32(sBl);
    uint32_t aoff[4], boff[2];
#pragma unroll
    for (int mt = 0; mt < 4; mt++)
        aoff[mt] = ((warp_m + mt * 16 + (g & 1) * 8 + r) * LDPAD + (g >> 1) * 8) * 2;
#pragma unroll
    for (int nt2 = 0; nt2 < 2; nt2++)
        boff[nt2] = ((warp_n + nt2 * 16 + (g >> 1) * 8 + r) * LDPAD + (g & 1) * 8) * 2;

    float acc[4][4][4];
#pragma unroll
    for (int i = 0; i < 4; i++)
#pragma unroll
        for (int j = 0; j < 4; j++)
#pragma unroll
            for (int t = 0; t < 4; t++) acc[i][j][t] = 0.f;

    const int NCH = K / 32;
    for (int ch = 0; ch < NCH; ch++) {
        const int k0 = ch * 32;
        // LDG (overlaps previous chunk's mma)
        uint4 vah0 = *(const uint4*)(pAh + k0);
        uint4 vah1 = *(const uint4*)(pAh + k0 + 8);
        uint4 val0 = *(const uint4*)(pAl + k0);
        uint4 val1 = *(const uint4*)(pAl + k0 + 8);
        uint4 vbh0 = *(const uint4*)(pBh + k0);
        uint4 vbh1 = *(const uint4*)(pBh + k0 + 8);
        uint4 vbl0 = *(const uint4*)(pBl + k0);
        uint4 vbl1 = *(const uint4*)(pBl + k0 + 8);

        __syncthreads();
        {
            __nv_bfloat16* d = &sAh[row][half * 16];
            *(uint4*)d = vah0; *(uint4*)(d + 8) = vah1;
            d = &sAl[row][half * 16];
            *(uint4*)d = val0; *(uint4*)(d + 8) = val1;
            d = &sBh[row][half * 16];
            *(uint4*)d = vbh0; *(uint4*)(d + 8) = vbh1;
            d = &sBl[row][half * 16];
            *(uint4*)d = vbl0; *(uint4*)(d + 8) = vbl1;
        }
        __syncthreads();

#pragma unroll
        for (int p = 0; p < 3; p++) {
            const uint32_t ua = (p == 2) ? uAl : uAh;
            const uint32_t ub = (p == 1) ? uBl : uBh;
#pragma unroll
            for (int ks = 0; ks < 2; ks++) {
                const uint32_t kadd = ks * 32;
                uint32_t afr[4][4], bfr[2][4];
#pragma unroll
                for (int mt = 0; mt < 4; mt++) ldsm_x4(ua + aoff[mt] + kadd, afr[mt]);
#pragma unroll
                for (int nt2 = 0; nt2 < 2; nt2++) ldsm_x4(ub + boff[nt2] + kadd, bfr[nt2]);
#pragma unroll
                for (int mt = 0; mt < 4; mt++)
#pragma unroll
                    for (int nt = 0; nt < 4; nt++)
                        mma_bf16(acc[mt][nt], afr[mt], bfr[nt >> 1] + (nt & 1) * 2);
            }
        }
    }

    const int erow = lane >> 2;
    const int ecol = (lane & 3) * 2;
#pragma unroll
    for (int mt = 0; mt < 4; mt++) {
#pragma unroll
        for (int nt = 0; nt < 4; nt++) {
            float* Cr = C + (size_t)(bm * 128 + warp_m + mt * 16 + erow) * N
                          + bn * 128 + warp_n + nt * 8 + ecol;
            *(float2*)Cr                   = make_float2(acc[mt][nt][0], acc[mt][nt][1]);
            *(float2*)(Cr + 8 * (size_t)N) = make_float2(acc[mt][nt][2], acc[mt][nt][3]);
        }
    }
}

// ---------------------------------------------------------------------------
// RoPE + scale + split: fp32 [B,S,nh,64] -> hi/lo bf16 (same layout)
// ---------------------------------------------------------------------------
__global__ void rope_split(const float* __restrict__ x,
                           __nv_bfloat16* __restrict__ oh,
                           __nv_bfloat16* __restrict__ ol,
                           const float* __restrict__ cs,
                           const float* __restrict__ sn,
                           int nh, float scale, int total_pairs)
{
    int p = blockIdx.x * blockDim.x + threadIdx.x;
    if (p >= total_pairs) return;
    int d2 = p & 31;
    int s  = (p / (32 * nh)) & (S_ - 1);
    float c  = cs[s * 32 + d2];
    float si = sn[s * 32 + d2];
    float2 xv = *(const float2*)(x + (size_t)p * 2);
    float rx = (xv.x * c - xv.y * si) * scale;
    float ry = (xv.x * si + xv.y * c) * scale;
    float l0, l1;
    float h0 = bf_hi(rx, &l0), h1 = bf_hi(ry, &l1);
    *(uint32_t*)(oh + (size_t)p * 2) = pk_bf2(h0, h1);
    *(uint32_t*)(ol + (size_t)p * 2) = pk_bf2(l0, l1);
}

// ---------------------------------------------------------------------------
// HMMA flash attention on pre-split bf16 q/k/v; writes pre-split bf16 output.
// CTA: 256 thr (8 warps), q-tile 128 (warp = m16), k-tile 64.
// ---------------------------------------------------------------------------
#define APAD 72
#define TILE_E (64 * APAD)

__global__ __launch_bounds__(256) void attn_mma(const __nv_bfloat16* __restrict__ qh,
                                                const __nv_bfloat16* __restrict__ ql,
                                                const __nv_bfloat16* __restrict__ kh,
                                                const __nv_bfloat16* __restrict__ kl,
                                                const __nv_bfloat16* __restrict__ vh,
                                                const __nv_bfloat16* __restrict__ vl,
                                                __nv_bfloat16* __restrict__ aoh,
                                                __nv_bfloat16* __restrict__ aol)
{
    __shared__ __align__(16) __nv_bfloat16 sm[4 * TILE_E];

    const int tid = threadIdx.x, lane = tid & 31, wid = tid >> 5;
    const int qt = blockIdx.x, h = blockIdx.y, b = blockIdx.z;
    const int kvh = h >> 1;
    const int lg = lane >> 3, lr = lane & 7;
    const int quad = lane >> 2, qd = lane & 3;

    const uint32_t uS = smem_u32(sm);

    // ---- Q stage: straight bf16 copies into smem ----
    {
        const int row = tid >> 1, half = tid & 1;
        const size_t gq = (((size_t)(b * S_ + qt * 128 + row)) * NH_ + h) * HD_ + half * 32;
        __nv_bfloat16* dh = sm + row * APAD + half * 32;
        __nv_bfloat16* dl = sm + 2 * TILE_E + row * APAD + half * 32;
#pragma unroll
        for (int i = 0; i < 4; i++) *(uint4*)(dh + i * 8) = *(const uint4*)(qh + gq + i * 8);
#pragma unroll
        for (int i = 0; i < 4; i++) *(uint4*)(dl + i * 8) = *(const uint4*)(ql + gq + i * 8);
    }
    __syncthreads();

    // ---- Q fragments (held for whole kernel) ----
    uint32_t qfh[4][4], qfl[4][4];
    {
        const int rowa = wid * 16 + (lg & 1) * 8 + lr;
#pragma unroll
        for (int kc = 0; kc < 4; kc++) {
            const uint32_t off = (uint32_t)(rowa * APAD + (lg >> 1) * 8 + kc * 16) * 2;
            ldsm_x4(uS + off, qfh[kc]);
            ldsm_x4(uS + 2 * TILE_E * 2 + off, qfl[kc]);
        }
    }

    const uint32_t uKh = uS;
    const uint32_t uKl = uS + TILE_E * 2;
    const uint32_t uVh = uS + 2 * TILE_E * 2;
    const uint32_t uVl = uS + 3 * TILE_E * 2;

    float o[8][4];
#pragma unroll
    for (int t = 0; t < 8; t++)
#pragma unroll
        for (int j = 0; j < 4; j++) o[t][j] = 0.f;
    float m0 = -1e30f, m1 = -1e30f, l0 = 0.f, l1 = 0.f;

    const int qbaseG = qt * 128 + wid * 16;
    const int lim0 = (qbaseG + quad) | 7;
    const int lim1 = (qbaseG + quad + 8) | 7;
    const int ntiles = 2 * qt + 2;

    const int krow = tid >> 2, kc4 = (tid & 3) * 16;
    __nv_bfloat16* skh = sm + krow * APAD + kc4;
    __nv_bfloat16* skl = skh + TILE_E;
    __nv_bfloat16* svh = skh + 2 * TILE_E;
    __nv_bfloat16* svl = skh + 3 * TILE_E;

    for (int kt = 0; kt < ntiles; kt++) {
        const size_t gkv = (((size_t)(b * S_ + kt * 64 + krow)) * NKV_ + kvh) * HD_ + kc4;
        uint4 rkh0 = *(const uint4*)(kh + gkv), rkh1 = *(const uint4*)(kh + gkv + 8);
        uint4 rkl0 = *(const uint4*)(kl + gkv), rkl1 = *(const uint4*)(kl + gkv + 8);
        uint4 rvh0 = *(const uint4*)(vh + gkv), rvh1 = *(const uint4*)(vh + gkv + 8);
        uint4 rvl0 = *(const uint4*)(vl + gkv), rvl1 = *(const uint4*)(vl + gkv + 8);

        __syncthreads();
        *(uint4*)skh = rkh0; *(uint4*)(skh + 8) = rkh1;
        *(uint4*)skl = rkl0; *(uint4*)(skl + 8) = rkl1;
        *(uint4*)svh = rvh0; *(uint4*)(svh + 8) = rvh1;
        *(uint4*)svl = rvl0; *(uint4*)(svl + 8) = rvl1;
        __syncthreads();

        if (kt * 64 > qbaseG + 15) continue;

        // ---- S = Q @ K^T ----
        float s[8][4];
#pragma unroll
        for (int t = 0; t < 8; t++)
#pragma unroll
            for (int j = 0; j < 4; j++) s[t][j] = 0.f;

#pragma unroll
        for (int kc = 0; kc < 4; kc++) {
#pragma unroll
            for (int nt2 = 0; nt2 < 4; nt2++) {
                const uint32_t boff =
                    (uint32_t)((nt2 * 16 + (lg >> 1) * 8 + lr) * APAD + (lg & 1) * 8 + kc * 16) * 2;
                uint32_t f[4];
                ldsm_x4(uKh + boff, f);
                mma_bf16(s[nt2 * 2],     qfh[kc], f);
                mma_bf16(s[nt2 * 2 + 1], qfh[kc], f + 2);
                mma_bf16(s[nt2 * 2],     qfl[kc], f);
                mma_bf16(s[nt2 * 2 + 1], qfl[kc], f + 2);
            }
#pragma unroll
            for (int nt2 = 0; nt2 < 4; nt2++) {
                const uint32_t boff =
                    (uint32_t)((nt2 * 16 + (lg >> 1) * 8 + lr) * APAD + (lg & 1) * 8 + kc * 16) * 2;
                uint32_t f[4];
                ldsm_x4(uKl + boff, f);
                mma_bf16(s[nt2 * 2],     qfh[kc], f);
                mma_bf16(s[nt2 * 2 + 1], qfh[kc], f + 2);
            }
        }

        // ---- block-causal mask ----
        if (kt * 64 + 63 > qbaseG + 7) {
#pragma unroll
            for (int t = 0; t < 8; t++) {
                const int key = kt * 64 + t * 8 + qd * 2;
                if (key     > lim0) s[t][0] = -1e30f;
                if (key + 1 > lim0) s[t][1] = -1e30f;
                if (key     > lim1) s[t][2] = -1e30f;
                if (key + 1 > lim1) s[t][3] = -1e30f;
            }
        }

        // ---- online softmax ----
        float mx0 = -1e30f, mx1 = -1e30f;
#pragma unroll
        for (int t = 0; t < 8; t++) {
            mx0 = fmaxf(mx0, fmaxf(s[t][0], s[t][1]));
            mx1 = fmaxf(mx1, fmaxf(s[t][2], s[t][3]));
        }
        mx0 = fmaxf(mx0, __shfl_xor_sync(0xffffffffu, mx0, 1));
        mx0 = fmaxf(mx0, __shfl_xor_sync(0xffffffffu, mx0, 2));
        mx1 = fmaxf(mx1, __shfl_xor_sync(0xffffffffu, mx1, 1));
        mx1 = fmaxf(mx1, __shfl_xor_sync(0xffffffffu, mx1, 2));

        const float mn0 = fmaxf(m0, mx0), mn1 = fmaxf(m1, mx1);
        const float a0 = __expf(m0 - mn0), a1 = __expf(m1 - mn1);
        l0 *= a0; l1 *= a1;
#pragma unroll
        for (int t = 0; t < 8; t++) {
            o[t][0] *= a0; o[t][1] *= a0; o[t][2] *= a1; o[t][3] *= a1;
        }
        float sl0 = 0.f, sl1 = 0.f;
#pragma unroll
        for (int t = 0; t < 8; t++) {
            s[t][0] = __expf(s[t][0] - mn0); s[t][1] = __expf(s[t][1] - mn0);
            s[t][2] = __expf(s[t][2] - mn1); s[t][3] = __expf(s[t][3] - mn1);
            sl0 += s[t][0] + s[t][1];
            sl1 += s[t][2] + s[t][3];
        }
        sl0 += __shfl_xor_sync(0xffffffffu, sl0, 1);
        sl0 += __shfl_xor_sync(0xffffffffu, sl0, 2);
        sl1 += __shfl_xor_sync(0xffffffffu, sl1, 1);
        sl1 += __shfl_xor_sync(0xffffffffu, sl1, 2);
        l0 += sl0; l1 += sl1;
        m0 = mn0; m1 = mn1;

        // ---- pack P hi/lo as A-fragments ----
        uint32_t ph[8][2], pl[8][2];
#pragma unroll
        for (int t = 0; t < 8; t++) {
            float r0, r1, r2, r3;
            float h0 = bf_hi(s[t][0], &r0), h1 = bf_hi(s[t][1], &r1);
            float h2 = bf_hi(s[t][2], &r2), h3 = bf_hi(s[t][3], &r3);
            ph[t][0] = pk_bf2(h0, h1); ph[t][1] = pk_bf2(h2, h3);
            pl[t][0] = pk_bf2(r0, r1); pl[t][1] = pk_bf2(r2, r3);
        }

        // ---- O += P @ V ----
#pragma unroll
        for (int kc = 0; kc < 4; kc++) {
            uint32_t ah[4] = {ph[2*kc][0], ph[2*kc][1], ph[2*kc+1][0], ph[2*kc+1][1]};
            uint32_t al[4] = {pl[2*kc][0], pl[2*kc][1], pl[2*kc+1][0], pl[2*kc+1][1]};
#pragma unroll
            for (int nt2 = 0; nt2 < 4; nt2++) {
                const uint32_t voff =
                    (uint32_t)((kc * 16 + (lg & 1) * 8 + lr) * APAD + nt2 * 16 + (lg >> 1) * 8) * 2;
                uint32_t f[4];
                ldsm_x4_t(uVh + voff, f);
                mma_bf16(o[nt2 * 2],     ah, f);
                mma_bf16(o[nt2 * 2 + 1], ah, f + 2);
                mma_bf16(o[nt2 * 2],     al, f);
                mma_bf16(o[nt2 * 2 + 1], al, f + 2);
            }
#pragma unroll
            for (int nt2 = 0; nt2 < 4; nt2++) {
                const uint32_t voff =
                    (uint32_t)((kc * 16 + (lg & 1) * 8 + lr) * APAD + nt2 * 16 + (lg >> 1) * 8) * 2;
                uint32_t f[4];
                ldsm_x4_t(uVl + voff, f);
                mma_bf16(o[nt2 * 2],     ah, f);
                mma_bf16(o[nt2 * 2 + 1], ah, f + 2);
            }
        }
    }

    // ---- epilogue: normalize + hi/lo split write ----
    const float inv0 = 1.f / l0, inv1 = 1.f / l1;
    const int row0 = qbaseG + quad;
    const size_t e0 = (((size_t)(b * S_ + row0)) * NH_ + h) * HD_ + qd * 2;
    const size_t e1 = (((size_t)(b * S_ + row0 + 8)) * NH_ + h) * HD_ + qd * 2;
#pragma unroll
    for (int t = 0; t < 8; t++) {
        float x0 = o[t][0] * inv0, x1 = o[t][1] * inv0;
        float y0 = o[t][2] * inv1, y1 = o[t][3] * inv1;
        float rx0, rx1, ry0, ry1;
        float hx0 = bf_hi(x0, &rx0), hx1 = bf_hi(x1, &rx1);
        float hy0 = bf_hi(y0, &ry0), hy1 = bf_hi(y1, &ry1);
        *(uint32_t*)(aoh + e0 + t * 8) = pk_bf2(hx0, hx1);
        *(uint32_t*)(aol + e0 + t * 8) = pk_bf2(rx0, rx1);
        *(uint32_t*)(aoh + e1 + t * 8) = pk_bf2(hy0, hy1);
        *(uint32_t*)(aol + e1 + t * 8) = pk_bf2(ry0, ry1);
    }
}

// ---------------------------------------------------------------------------
extern "C" void kernel_launch(void* const* d_in, const int* in_sizes, int n_in,
                              void* d_out, int out_size)
{
    const float* x   = (const float*)d_in[0];
    const float* wq  = (const float*)d_in[1];
    const float* wk  = (const float*)d_in[2];
    const float* wv  = (const float*)d_in[3];
    const float* wo  = (const float*)d_in[4];
    const float* fcc = (const float*)d_in[5];
    const float* fcs = (const float*)d_in[6];
    (void)in_sizes; (void)n_in;

    float *q, *k, *v;
    __nv_bfloat16 *xh, *xl, *wqh, *wql, *wkh, *wkl, *wvh, *wvl, *woh, *wol;
    __nv_bfloat16 *qh, *ql, *kh, *kl, *vh, *vl, *aoh, *aol;
    cudaGetSymbolAddress((void**)&q,   g_q);
    cudaGetSymbolAddress((void**)&k,   g_k);
    cudaGetSymbolAddress((void**)&v,   g_v);
    cudaGetSymbolAddress((void**)&xh,  g_xh);
    cudaGetSymbolAddress((void**)&xl,  g_xl);
    cudaGetSymbolAddress((void**)&wqh, g_wqh);
    cudaGetSymbolAddress((void**)&wql, g_wql);
    cudaGetSymbolAddress((void**)&wkh, g_wkh);
    cudaGetSymbolAddress((void**)&wkl, g_wkl);
    cudaGetSymbolAddress((void**)&wvh, g_wvh);
    cudaGetSymbolAddress((void**)&wvl, g_wvl);
    cudaGetSymbolAddress((void**)&woh, g_woh);
    cudaGetSymbolAddress((void**)&wol, g_wol);
    cudaGetSymbolAddress((void**)&qh,  g_qh);
    cudaGetSymbolAddress((void**)&ql,  g_ql);
    cudaGetSymbolAddress((void**)&kh,  g_kh);
    cudaGetSymbolAddress((void**)&kl,  g_kl);
    cudaGetSymbolAddress((void**)&vh,  g_vh);
    cudaGetSymbolAddress((void**)&vl,  g_vl);
    cudaGetSymbolAddress((void**)&aoh, g_aoh);
    cudaGetSymbolAddress((void**)&aol, g_aol);

    const int M = M_;   // 8192

    // input splits
    split_f32<<<(M * D_ / 4 + 255) / 256, 256>>>(x, xh, xl, M * D_ / 4);
    trans_split<<<dim3(D_/32,  D_/32), dim3(32, 8)>>>(wq, wqh, wql, D_,   D_);
    trans_split<<<dim3(D_/64,  D_/32), dim3(32, 8)>>>(wk, wkh, wkl, D_/2, D_);
    trans_split<<<dim3(D_/64,  D_/32), dim3(32, 8)>>>(wv, wvh, wvl, D_/2, D_);
    trans_split<<<dim3(D_/32,  D_/32), dim3(32, 8)>>>(wo, woh, wol, D_,   D_);

    // QKV projections
    hgemm_s<<<dim3(NH_*HD_/128,  M/128), 256>>>(xh, xl, wqh, wql, q, NH_*HD_,  D_);
    hgemm_s<<<dim3(NKV_*HD_/128, M/128), 256>>>(xh, xl, wkh, wkl, k, NKV_*HD_, D_);
    hgemm_s<<<dim3(NKV_*HD_/128, M/128), 256>>>(xh, xl, wvh, wvl, v, NKV_*HD_, D_);

    // RoPE + split (q scaled by 1/8); v split
    {
        int qp = M * NH_ * (HD_ / 2);
        int kp = M * NKV_ * (HD_ / 2);
        rope_split<<<(qp + 255) / 256, 256>>>(q, qh, ql, fcc, fcs, NH_,  0.125f, qp);
        rope_split<<<(kp + 255) / 256, 256>>>(k, kh, kl, fcc, fcs, NKV_, 1.0f,   kp);
        split_f32<<<(M * NKV_ * HD_ / 4 + 255) / 256, 256>>>(v, vh, vl, M * NKV_ * HD_ / 4);
    }

    // Attention
    attn_mma<<<dim3(S_/128, NH_, B_), 256>>>(qh, ql, kh, kl, vh, vl, aoh, aol);

    // Output projection
    hgemm_s<<<dim3(D_/128, M/128), 256>>>(aoh, aol, woh, wol, (float*)d_out, D_, D_);
    (void)out_size;
}

// round 13
// speedup vs baseline: 1.8012x; 1.0510x over previous
#include <cuda_runtime.h>
#include <cuda_bf16.h>
#include <math.h>
#include <stdint.h>

#define B_ 8
#define S_ 1024
#define D_ 1024
#define NH_ 16
#define NKV_ 8
#define HD_ 64
#define M_ (B_*S_)

// ---------------------------------------------------------------------------
// Scratch (allocation-free rule: __device__ globals)
// ---------------------------------------------------------------------------
__device__ float g_q[M_*NH_*HD_];
__device__ float g_k[M_*NKV_*HD_];
__device__ float g_v[M_*NKV_*HD_];

__device__ __nv_bfloat16 g_xh[M_*D_],  g_xl[M_*D_];
__device__ __nv_bfloat16 g_wqh[D_*D_], g_wql[D_*D_];
__device__ __nv_bfloat16 g_wkh[(D_/2)*D_], g_wkl[(D_/2)*D_];
__device__ __nv_bfloat16 g_wvh[(D_/2)*D_], g_wvl[(D_/2)*D_];
__device__ __nv_bfloat16 g_woh[D_*D_], g_wol[D_*D_];
__device__ __nv_bfloat16 g_qh[M_*NH_*HD_],  g_ql[M_*NH_*HD_];
__device__ __nv_bfloat16 g_kh[M_*NKV_*HD_], g_kl[M_*NKV_*HD_];
__device__ __nv_bfloat16 g_vh[M_*NKV_*HD_], g_vl[M_*NKV_*HD_];
__device__ __nv_bfloat16 g_aoh[M_*NH_*HD_], g_aol[M_*NH_*HD_];

// ---------------------------------------------------------------------------
// helpers
// ---------------------------------------------------------------------------
__device__ __forceinline__ uint32_t smem_u32(const void* p) {
    uint32_t a;
    asm("{ .reg .u64 t; cvta.to.shared.u64 t, %1; cvt.u32.u64 %0, t; }" : "=r"(a) : "l"(p));
    return a;
}
__device__ __forceinline__ void ldsm_x4(uint32_t addr, uint32_t* d) {
    asm volatile("ldmatrix.sync.aligned.m8n8.x4.shared.b16 {%0,%1,%2,%3}, [%4];"
                 : "=r"(d[0]), "=r"(d[1]), "=r"(d[2]), "=r"(d[3]) : "r"(addr));
}
__device__ __forceinline__ void ldsm_x4_t(uint32_t addr, uint32_t* d) {
    asm volatile("ldmatrix.sync.aligned.m8n8.x4.trans.shared.b16 {%0,%1,%2,%3}, [%4];"
                 : "=r"(d[0]), "=r"(d[1]), "=r"(d[2]), "=r"(d[3]) : "r"(addr));
}
__device__ __forceinline__ void mma_bf16(float* c, const uint32_t* a, const uint32_t* b) {
    asm volatile(
        "mma.sync.aligned.m16n8k16.row.col.f32.bf16.bf16.f32 "
        "{%0,%1,%2,%3}, {%4,%5,%6,%7}, {%8,%9}, {%0,%1,%2,%3};"
        : "+f"(c[0]), "+f"(c[1]), "+f"(c[2]), "+f"(c[3])
        : "r"(a[0]), "r"(a[1]), "r"(a[2]), "r"(a[3]), "r"(b[0]), "r"(b[1]));
}
__device__ __forceinline__ void cp16(uint32_t dst, const void* src) {
    asm volatile("cp.async.cg.shared.global [%0], [%1], 16;" :: "r"(dst), "l"(src) : "memory");
}
__device__ __forceinline__ void cp_commit() {
    asm volatile("cp.async.commit_group;" ::: "memory");
}
template<int N> __device__ __forceinline__ void cp_wait() {
    asm volatile("cp.async.wait_group %0;" :: "n"(N) : "memory");
}
__device__ __forceinline__ uint32_t pk_bf2(float lo, float hi) {
    __nv_bfloat162 t;
    t.x = __float2bfloat16(lo);
    t.y = __float2bfloat16(hi);
    return *reinterpret_cast<uint32_t*>(&t);
}
__device__ __forceinline__ float bf_hi(float x, float* rem) {
    __nv_bfloat16 h = __float2bfloat16(x);
    float hf = __bfloat162float(h);
    *rem = x - hf;
    return hf;
}

// ---------------------------------------------------------------------------
// elementwise split
// ---------------------------------------------------------------------------
__global__ void split_f32(const float* __restrict__ src,
                          __nv_bfloat16* __restrict__ dh,
                          __nv_bfloat16* __restrict__ dl, int n4)
{
    int i = blockIdx.x * blockDim.x + threadIdx.x;
    if (i >= n4) return;
    float4 f = *(const float4*)(src + (size_t)i * 4);
    float r0, r1, r2, r3;
    float h0 = bf_hi(f.x, &r0), h1 = bf_hi(f.y, &r1);
    float h2 = bf_hi(f.z, &r2), h3 = bf_hi(f.w, &r3);
    *(uint2*)(dh + (size_t)i * 4) = make_uint2(pk_bf2(h0, h1), pk_bf2(h2, h3));
    *(uint2*)(dl + (size_t)i * 4) = make_uint2(pk_bf2(r0, r1), pk_bf2(r2, r3));
}

// ---------------------------------------------------------------------------
// transpose + split
// ---------------------------------------------------------------------------
__global__ void trans_split(const float* __restrict__ W,
                            __nv_bfloat16* __restrict__ Th,
                            __nv_bfloat16* __restrict__ Tl, int N, int K)
{
    __shared__ float t[32][33];
    const int n0 = blockIdx.x * 32, k0 = blockIdx.y * 32;
    const int tx = threadIdx.x, ty = threadIdx.y;
#pragma unroll
    for (int i = 0; i < 4; i++)
        t[ty + i * 8][tx] = W[(size_t)(k0 + ty + i * 8) * N + n0 + tx];
    __syncthreads();
#pragma unroll
    for (int i = 0; i < 4; i++) {
        float x = t[tx][ty + i * 8];
        float r;
        float h = bf_hi(x, &r);
        size_t o = (size_t)(n0 + ty + i * 8) * K + k0 + tx;
        Th[o] = __float2bfloat16(h);
        Tl[o] = __float2bfloat16(r);
    }
}

// ---------------------------------------------------------------------------
// HMMA GEMM, cp.async 2-stage double-buffered, pre-split bf16 operands.
// C[M,N] = (Ah+Al)[M,K] @ (Bh+Bl)^T[N,K], 3 passes. 128x128 tile, BK=32.
// dynamic smem: 2 stages x 4 tiles x [128][LDPAD] bf16 = 80KB.
// ---------------------------------------------------------------------------
#define LDPAD 40
#define HG_TILEB (128 * LDPAD * 2)     // bytes per tile (10240)
#define HG_STAGEB (4 * HG_TILEB)       // bytes per stage (40960)
#define HG_SMEM (2 * HG_STAGEB)        // 81920

__global__ __launch_bounds__(256, 2) void hgemm_s(const __nv_bfloat16* __restrict__ Ah,
                                                  const __nv_bfloat16* __restrict__ Al,
                                                  const __nv_bfloat16* __restrict__ Bh,
                                                  const __nv_bfloat16* __restrict__ Bl,
                                                  float* __restrict__ C,
                                                  int N, int K)
{
    extern __shared__ __align__(16) char dsm[];
    const uint32_t uD = smem_u32(dsm);

    const int tid = threadIdx.x, lane = tid & 31, wid = tid >> 5;
    const int bn = blockIdx.x, bm = blockIdx.y;
    const int warp_m = (wid & 1) * 64;
    const int warp_n = (wid >> 1) * 32;

    const int row  = tid >> 1;
    const int half = tid & 1;
    const __nv_bfloat16* pAh = Ah + (size_t)(bm * 128 + row) * K + half * 16;
    const __nv_bfloat16* pAl = Al + (size_t)(bm * 128 + row) * K + half * 16;
    const __nv_bfloat16* pBh = Bh + (size_t)(bn * 128 + row) * K + half * 16;
    const __nv_bfloat16* pBl = Bl + (size_t)(bn * 128 + row) * K + half * 16;
    const uint32_t fill_off = (uint32_t)(row * LDPAD + half * 16) * 2;

    const int g = lane >> 3, r = lane & 7;
    uint32_t aoff[4], boff[2];
#pragma unroll
    for (int mt = 0; mt < 4; mt++)
        aoff[mt] = ((warp_m + mt * 16 + (g & 1) * 8 + r) * LDPAD + (g >> 1) * 8) * 2;
#pragma unroll
    for (int nt2 = 0; nt2 < 2; nt2++)
        boff[nt2] = ((warp_n + nt2 * 16 + (g >> 1) * 8 + r) * LDPAD + (g & 1) * 8) * 2;

    float acc[4][4][4];
#pragma unroll
    for (int i = 0; i < 4; i++)
#pragma unroll
        for (int j = 0; j < 4; j++)
#pragma unroll
            for (int t = 0; t < 4; t++) acc[i][j][t] = 0.f;

    const int NCH = K / 32;

    // prologue: stage 0
    {
        const uint32_t d = uD + fill_off;
        cp16(d,                    pAh);      cp16(d + 16,                pAh + 8);
        cp16(d + HG_TILEB,         pAl);      cp16(d + HG_TILEB + 16,     pAl + 8);
        cp16(d + 2 * HG_TILEB,     pBh);      cp16(d + 2 * HG_TILEB + 16, pBh + 8);
        cp16(d + 3 * HG_TILEB,     pBl);      cp16(d + 3 * HG_TILEB + 16, pBl + 8);
        cp_commit();
    }

    for (int ch = 0; ch < NCH; ch++) {
        if (ch + 1 < NCH) {
            const int k1 = (ch + 1) * 32;
            const uint32_t d = uD + ((ch + 1) & 1) * HG_STAGEB + fill_off;
            cp16(d,                    pAh + k1);      cp16(d + 16,                pAh + k1 + 8);
            cp16(d + HG_TILEB,         pAl + k1);      cp16(d + HG_TILEB + 16,     pAl + k1 + 8);
            cp16(d + 2 * HG_TILEB,     pBh + k1);      cp16(d + 2 * HG_TILEB + 16, pBh + k1 + 8);
            cp16(d + 3 * HG_TILEB,     pBl + k1);      cp16(d + 3 * HG_TILEB + 16, pBl + k1 + 8);
            cp_commit();
            cp_wait<1>();
        } else {
            cp_wait<0>();
        }
        __syncthreads();

        const uint32_t uSt = uD + (ch & 1) * HG_STAGEB;
        const uint32_t uAh = uSt, uAl = uSt + HG_TILEB;
        const uint32_t uBh = uSt + 2 * HG_TILEB, uBl = uSt + 3 * HG_TILEB;
#pragma unroll
        for (int p = 0; p < 3; p++) {
            const uint32_t ua = (p == 2) ? uAl : uAh;
            const uint32_t ub = (p == 1) ? uBl : uBh;
#pragma unroll
            for (int ks = 0; ks < 2; ks++) {
                const uint32_t kadd = ks * 32;
                uint32_t afr[4][4], bfr[2][4];
#pragma unroll
                for (int mt = 0; mt < 4; mt++) ldsm_x4(ua + aoff[mt] + kadd, afr[mt]);
#pragma unroll
                for (int nt2 = 0; nt2 < 2; nt2++) ldsm_x4(ub + boff[nt2] + kadd, bfr[nt2]);
#pragma unroll
                for (int mt = 0; mt < 4; mt++)
#pragma unroll
                    for (int nt = 0; nt < 4; nt++)
                        mma_bf16(acc[mt][nt], afr[mt], bfr[nt >> 1] + (nt & 1) * 2);
            }
        }
        __syncthreads();
    }

    const int erow = lane >> 2;
    const int ecol = (lane & 3) * 2;
#pragma unroll
    for (int mt = 0; mt < 4; mt++) {
#pragma unroll
        for (int nt = 0; nt < 4; nt++) {
            float* Cr = C + (size_t)(bm * 128 + warp_m + mt * 16 + erow) * N
                          + bn * 128 + warp_n + nt * 8 + ecol;
            *(float2*)Cr                   = make_float2(acc[mt][nt][0], acc[mt][nt][1]);
            *(float2*)(Cr + 8 * (size_t)N) = make_float2(acc[mt][nt][2], acc[mt][nt][3]);
        }
    }
}

// ---------------------------------------------------------------------------
// RoPE + scale + split
// ---------------------------------------------------------------------------
__global__ void rope_split(const float* __restrict__ x,
                           __nv_bfloat16* __restrict__ oh,
                           __nv_bfloat16* __restrict__ ol,
                           const float* __restrict__ cs,
                           const float* __restrict__ sn,
                           int nh, float scale, int total_pairs)
{
    int p = blockIdx.x * blockDim.x + threadIdx.x;
    if (p >= total_pairs) return;
    int d2 = p & 31;
    int s  = (p / (32 * nh)) & (S_ - 1);
    float c  = cs[s * 32 + d2];
    float si = sn[s * 32 + d2];
    float2 xv = *(const float2*)(x + (size_t)p * 2);
    float rx = (xv.x * c - xv.y * si) * scale;
    float ry = (xv.x * si + xv.y * c) * scale;
    float l0, l1;
    float h0 = bf_hi(rx, &l0), h1 = bf_hi(ry, &l1);
    *(uint32_t*)(oh + (size_t)p * 2) = pk_bf2(h0, h1);
    *(uint32_t*)(ol + (size_t)p * 2) = pk_bf2(l0, l1);
}

// ---------------------------------------------------------------------------
// HMMA flash attention, cp.async 2-stage K/V pipeline, pre-split bf16.
// dynamic smem: 2 stages x 4 tiles x [64][APAD] bf16 = 72KB.
// ---------------------------------------------------------------------------
#define APAD 72
#define TILE_E (64 * APAD)
#define AT_TILEB (TILE_E * 2)          // 9216
#define AT_STAGEB (4 * AT_TILEB)       // 36864
#define AT_SMEM (2 * AT_STAGEB)        // 73728

__global__ __launch_bounds__(256) void attn_mma(const __nv_bfloat16* __restrict__ qh,
                                                const __nv_bfloat16* __restrict__ ql,
                                                const __nv_bfloat16* __restrict__ kh,
                                                const __nv_bfloat16* __restrict__ kl,
                                                const __nv_bfloat16* __restrict__ vh,
                                                const __nv_bfloat16* __restrict__ vl,
                                                __nv_bfloat16* __restrict__ aoh,
                                                __nv_bfloat16* __restrict__ aol)
{
    extern __shared__ __align__(16) char dsm[];
    __nv_bfloat16* sm = (__nv_bfloat16*)dsm;
    const uint32_t uD = smem_u32(dsm);

    const int tid = threadIdx.x, lane = tid & 31, wid = tid >> 5;
    const int qt = blockIdx.x, h = blockIdx.y, b = blockIdx.z;
    const int kvh = h >> 1;
    const int lg = lane >> 3, lr = lane & 7;
    const int quad = lane >> 2, qd = lane & 3;

    // ---- Q stage into stage-0 region ----
    {
        const int row = tid >> 1, half = tid & 1;
        const size_t gq = (((size_t)(b * S_ + qt * 128 + row)) * NH_ + h) * HD_ + half * 32;
        __nv_bfloat16* dh = sm + row * APAD + half * 32;
        __nv_bfloat16* dl = sm + 2 * TILE_E + row * APAD + half * 32;
#pragma unroll
        for (int i = 0; i < 4; i++) *(uint4*)(dh + i * 8) = *(const uint4*)(qh + gq + i * 8);
#pragma unroll
        for (int i = 0; i < 4; i++) *(uint4*)(dl + i * 8) = *(const uint4*)(ql + gq + i * 8);
    }
    __syncthreads();

    uint32_t qfh[4][4], qfl[4][4];
    {
        const int rowa = wid * 16 + (lg & 1) * 8 + lr;
#pragma unroll
        for (int kc = 0; kc < 4; kc++) {
            const uint32_t off = (uint32_t)(rowa * APAD + (lg >> 1) * 8 + kc * 16) * 2;
            ldsm_x4(uD + off, qfh[kc]);
            ldsm_x4(uD + 2 * AT_TILEB + off, qfl[kc]);
        }
    }
    __syncthreads();   // Q reads done before cp.async overwrites stage 0

    float o[8][4];
#pragma unroll
    for (int t = 0; t < 8; t++)
#pragma unroll
        for (int j = 0; j < 4; j++) o[t][j] = 0.f;
    float m0 = -1e30f, m1 = -1e30f, l0 = 0.f, l1 = 0.f;

    const int qbaseG = qt * 128 + wid * 16;
    const int lim0 = (qbaseG + quad) | 7;
    const int lim1 = (qbaseG + quad + 8) | 7;
    const int ntiles = 2 * qt + 2;

    const int krow = tid >> 2, kc4 = (tid & 3) * 16;
    const uint32_t fill_off = (uint32_t)(krow * APAD + kc4) * 2;

    // prologue: tile 0 -> stage 0
    {
        const size_t gkv = (((size_t)(b * S_ + krow)) * NKV_ + kvh) * HD_ + kc4;
        const uint32_t d = uD + fill_off;
        cp16(d,                kh + gkv); cp16(d + 16,                kh + gkv + 8);
        cp16(d + AT_TILEB,     kl + gkv); cp16(d + AT_TILEB + 16,     kl + gkv + 8);
        cp16(d + 2 * AT_TILEB, vh + gkv); cp16(d + 2 * AT_TILEB + 16, vh + gkv + 8);
        cp16(d + 3 * AT_TILEB, vl + gkv); cp16(d + 3 * AT_TILEB + 16, vl + gkv + 8);
        cp_commit();
    }

    for (int kt = 0; kt < ntiles; kt++) {
        if (kt + 1 < ntiles) {
            const size_t gkv = (((size_t)(b * S_ + (kt + 1) * 64 + krow)) * NKV_ + kvh) * HD_ + kc4;
            const uint32_t d = uD + ((kt + 1) & 1) * AT_STAGEB + fill_off;
            cp16(d,                kh + gkv); cp16(d + 16,                kh + gkv + 8);
            cp16(d + AT_TILEB,     kl + gkv); cp16(d + AT_TILEB + 16,     kl + gkv + 8);
            cp16(d + 2 * AT_TILEB, vh + gkv); cp16(d + 2 * AT_TILEB + 16, vh + gkv + 8);
            cp16(d + 3 * AT_TILEB, vl + gkv); cp16(d + 3 * AT_TILEB + 16, vl + gkv + 8);
            cp_commit();
            cp_wait<1>();
        } else {
            cp_wait<0>();
        }
        __syncthreads();

        if (kt * 64 <= qbaseG + 15) {
            const uint32_t uSt = uD + (kt & 1) * AT_STAGEB;
            const uint32_t uKh = uSt, uKl = uSt + AT_TILEB;
            const uint32_t uVh = uSt + 2 * AT_TILEB, uVl = uSt + 3 * AT_TILEB;

            // ---- S = Q @ K^T ----
            float s[8][4];
#pragma unroll
            for (int t = 0; t < 8; t++)
#pragma unroll
                for (int j = 0; j < 4; j++) s[t][j] = 0.f;

#pragma unroll
            for (int kc = 0; kc < 4; kc++) {
#pragma unroll
                for (int nt2 = 0; nt2 < 4; nt2++) {
                    const uint32_t boff =
                        (uint32_t)((nt2 * 16 + (lg >> 1) * 8 + lr) * APAD + (lg & 1) * 8 + kc * 16) * 2;
                    uint32_t f[4];
                    ldsm_x4(uKh + boff, f);
                    mma_bf16(s[nt2 * 2],     qfh[kc], f);
                    mma_bf16(s[nt2 * 2 + 1], qfh[kc], f + 2);
                    mma_bf16(s[nt2 * 2],     qfl[kc], f);
                    mma_bf16(s[nt2 * 2 + 1], qfl[kc], f + 2);
                }
#pragma unroll
                for (int nt2 = 0; nt2 < 4; nt2++) {
                    const uint32_t boff =
                        (uint32_t)((nt2 * 16 + (lg >> 1) * 8 + lr) * APAD + (lg & 1) * 8 + kc * 16) * 2;
                    uint32_t f[4];
                    ldsm_x4(uKl + boff, f);
                    mma_bf16(s[nt2 * 2],     qfh[kc], f);
                    mma_bf16(s[nt2 * 2 + 1], qfh[kc], f + 2);
                }
            }

            // ---- block-causal mask ----
            if (kt * 64 + 63 > qbaseG + 7) {
#pragma unroll
                for (int t = 0; t < 8; t++) {
                    const int key = kt * 64 + t * 8 + qd * 2;
                    if (key     > lim0) s[t][0] = -1e30f;
                    if (key + 1 > lim0) s[t][1] = -1e30f;
                    if (key     > lim1) s[t][2] = -1e30f;
                    if (key + 1 > lim1) s[t][3] = -1e30f;
                }
            }

            // ---- online softmax ----
            float mx0 = -1e30f, mx1 = -1e30f;
#pragma unroll
            for (int t = 0; t < 8; t++) {
                mx0 = fmaxf(mx0, fmaxf(s[t][0], s[t][1]));
                mx1 = fmaxf(mx1, fmaxf(s[t][2], s[t][3]));
            }
            mx0 = fmaxf(mx0, __shfl_xor_sync(0xffffffffu, mx0, 1));
            mx0 = fmaxf(mx0, __shfl_xor_sync(0xffffffffu, mx0, 2));
            mx1 = fmaxf(mx1, __shfl_xor_sync(0xffffffffu, mx1, 1));
            mx1 = fmaxf(mx1, __shfl_xor_sync(0xffffffffu, mx1, 2));

            const float mn0 = fmaxf(m0, mx0), mn1 = fmaxf(m1, mx1);
            const float a0 = __expf(m0 - mn0), a1 = __expf(m1 - mn1);
            l0 *= a0; l1 *= a1;
#pragma unroll
            for (int t = 0; t < 8; t++) {
                o[t][0] *= a0; o[t][1] *= a0; o[t][2] *= a1; o[t][3] *= a1;
            }
            float sl0 = 0.f, sl1 = 0.f;
#pragma unroll
            for (int t = 0; t < 8; t++) {
                s[t][0] = __expf(s[t][0] - mn0); s[t][1] = __expf(s[t][1] - mn0);
                s[t][2] = __expf(s[t][2] - mn1); s[t][3] = __expf(s[t][3] - mn1);
                sl0 += s[t][0] + s[t][1];
                sl1 += s[t][2] + s[t][3];
            }
            sl0 += __shfl_xor_sync(0xffffffffu, sl0, 1);
            sl0 += __shfl_xor_sync(0xffffffffu, sl0, 2);
            sl1 += __shfl_xor_sync(0xffffffffu, sl1, 1);
            sl1 += __shfl_xor_sync(0xffffffffu, sl1, 2);
            l0 += sl0; l1 += sl1;
            m0 = mn0; m1 = mn1;

            // ---- pack P hi/lo as A-fragments ----
            uint32_t ph[8][2], pl[8][2];
#pragma unroll
            for (int t = 0; t < 8; t++) {
                float r0, r1, r2, r3;
                float h0 = bf_hi(s[t][0], &r0), h1 = bf_hi(s[t][1], &r1);
                float h2 = bf_hi(s[t][2], &r2), h3 = bf_hi(s[t][3], &r3);
                ph[t][0] = pk_bf2(h0, h1); ph[t][1] = pk_bf2(h2, h3);
                pl[t][0] = pk_bf2(r0, r1); pl[t][1] = pk_bf2(r2, r3);
            }

            // ---- O += P @ V ----
#pragma unroll
            for (int kc = 0; kc < 4; kc++) {
                uint32_t ah[4] = {ph[2*kc][0], ph[2*kc][1], ph[2*kc+1][0], ph[2*kc+1][1]};
                uint32_t al[4] = {pl[2*kc][0], pl[2*kc][1], pl[2*kc+1][0], pl[2*kc+1][1]};
#pragma unroll
                for (int nt2 = 0; nt2 < 4; nt2++) {
                    const uint32_t voff =
                        (uint32_t)((kc * 16 + (lg & 1) * 8 + lr) * APAD + nt2 * 16 + (lg >> 1) * 8) * 2;
                    uint32_t f[4];
                    ldsm_x4_t(uVh + voff, f);
                    mma_bf16(o[nt2 * 2],     ah, f);
                    mma_bf16(o[nt2 * 2 + 1], ah, f + 2);
                    mma_bf16(o[nt2 * 2],     al, f);
                    mma_bf16(o[nt2 * 2 + 1], al, f + 2);
                }
#pragma unroll
                for (int nt2 = 0; nt2 < 4; nt2++) {
                    const uint32_t voff =
                        (uint32_t)((kc * 16 + (lg & 1) * 8 + lr) * APAD + nt2 * 16 + (lg >> 1) * 8) * 2;
                    uint32_t f[4];
                    ldsm_x4_t(uVl + voff, f);
                    mma_bf16(o[nt2 * 2],     ah, f);
                    mma_bf16(o[nt2 * 2 + 1], ah, f + 2);
                }
            }
        }
        __syncthreads();
    }

    // ---- epilogue: normalize + hi/lo split write ----
    const float inv0 = 1.f / l0, inv1 = 1.f / l1;
    const int row0 = qbaseG + quad;
    const size_t e0 = (((size_t)(b * S_ + row0)) * NH_ + h) * HD_ + qd * 2;
    const size_t e1 = (((size_t)(b * S_ + row0 + 8)) * NH_ + h) * HD_ + qd * 2;
#pragma unroll
    for (int t = 0; t < 8; t++) {
        float x0 = o[t][0] * inv0, x1 = o[t][1] * inv0;
        float y0 = o[t][2] * inv1, y1 = o[t][3] * inv1;
        float rx0, rx1, ry0, ry1;
        float hx0 = bf_hi(x0, &rx0), hx1 = bf_hi(x1, &rx1);
        float hy0 = bf_hi(y0, &ry0), hy1 = bf_hi(y1, &ry1);
        *(uint32_t*)(aoh + e0 + t * 8) = pk_bf2(hx0, hx1);
        *(uint32_t*)(aol + e0 + t * 8) = pk_bf2(rx0, rx1);
        *(uint32_t*)(aoh + e1 + t * 8) = pk_bf2(hy0, hy1);
        *(uint32_t*)(aol + e1 + t * 8) = pk_bf2(ry0, ry1);
    }
}

// ---------------------------------------------------------------------------
extern "C" void kernel_launch(void* const* d_in, const int* in_sizes, int n_in,
                              void* d_out, int out_size)
{
    const float* x   = (const float*)d_in[0];
    const float* wq  = (const float*)d_in[1];
    const float* wk  = (const float*)d_in[2];
    const float* wv  = (const float*)d_in[3];
    const float* wo  = (const float*)d_in[4];
    const float* fcc = (const float*)d_in[5];
    const float* fcs = (const float*)d_in[6];
    (void)in_sizes; (void)n_in;

    float *q, *k, *v;
    __nv_bfloat16 *xh, *xl, *wqh, *wql, *wkh, *wkl, *wvh, *wvl, *woh, *wol;
    __nv_bfloat16 *qh, *ql, *kh, *kl, *vh, *vl, *aoh, *aol;
    cudaGetSymbolAddress((void**)&q,   g_q);
    cudaGetSymbolAddress((void**)&k,   g_k);
    cudaGetSymbolAddress((void**)&v,   g_v);
    cudaGetSymbolAddress((void**)&xh,  g_xh);
    cudaGetSymbolAddress((void**)&xl,  g_xl);
    cudaGetSymbolAddress((void**)&wqh, g_wqh);
    cudaGetSymbolAddress((void**)&wql, g_wql);
    cudaGetSymbolAddress((void**)&wkh, g_wkh);
    cudaGetSymbolAddress((void**)&wkl, g_wkl);
    cudaGetSymbolAddress((void**)&wvh, g_wvh);
    cudaGetSymbolAddress((void**)&wvl, g_wvl);
    cudaGetSymbolAddress((void**)&woh, g_woh);
    cudaGetSymbolAddress((void**)&wol, g_wol);
    cudaGetSymbolAddress((void**)&qh,  g_qh);
    cudaGetSymbolAddress((void**)&ql,  g_ql);
    cudaGetSymbolAddress((void**)&kh,  g_kh);
    cudaGetSymbolAddress((void**)&kl,  g_kl);
    cudaGetSymbolAddress((void**)&vh,  g_vh);
    cudaGetSymbolAddress((void**)&vl,  g_vl);
    cudaGetSymbolAddress((void**)&aoh, g_aoh);
    cudaGetSymbolAddress((void**)&aol, g_aol);

    cudaFuncSetAttribute(hgemm_s,  cudaFuncAttributeMaxDynamicSharedMemorySize, HG_SMEM);
    cudaFuncSetAttribute(attn_mma, cudaFuncAttributeMaxDynamicSharedMemorySize, AT_SMEM);

    const int M = M_;   // 8192

    // input splits
    split_f32<<<(M * D_ / 4 + 255) / 256, 256>>>(x, xh, xl, M * D_ / 4);
    trans_split<<<dim3(D_/32,  D_/32), dim3(32, 8)>>>(wq, wqh, wql, D_,   D_);
    trans_split<<<dim3(D_/64,  D_/32), dim3(32, 8)>>>(wk, wkh, wkl, D_/2, D_);
    trans_split<<<dim3(D_/64,  D_/32), dim3(32, 8)>>>(wv, wvh, wvl, D_/2, D_);
    trans_split<<<dim3(D_/32,  D_/32), dim3(32, 8)>>>(wo, woh, wol, D_,   D_);

    // QKV projections
    hgemm_s<<<dim3(NH_*HD_/128,  M/128), 256, HG_SMEM>>>(xh, xl, wqh, wql, q, NH_*HD_,  D_);
    hgemm_s<<<dim3(NKV_*HD_/128, M/128), 256, HG_SMEM>>>(xh, xl, wkh, wkl, k, NKV_*HD_, D_);
    hgemm_s<<<dim3(NKV_*HD_/128, M/128), 256, HG_SMEM>>>(xh, xl, wvh, wvl, v, NKV_*HD_, D_);

    // RoPE + split (q scaled by 1/8); v split
    {
        int qp = M * NH_ * (HD_ / 2);
        int kp = M * NKV_ * (HD_ / 2);
        rope_split<<<(qp + 255) / 256, 256>>>(q, qh, ql, fcc, fcs, NH_,  0.125f, qp);
        rope_split<<<(kp + 255) / 256, 256>>>(k, kh, kl, fcc, fcs, NKV_, 1.0f,   kp);
        split_f32<<<(M * NKV_ * HD_ / 4 + 255) / 256, 256>>>(v, vh, vl, M * NKV_ * HD_ / 4);
    }

    // Attention
    attn_mma<<<dim3(S_/128, NH_, B_), 256, AT_SMEM>>>(qh, ql, kh, kl, vh, vl, aoh, aol);

    // Output projection
    hgemm_s<<<dim3(D_/128, M/128), 256, HG_SMEM>>>(aoh, aol, woh, wol, (float*)d_out, D_, D_);
    (void)out_size;
}

// round 14
// speedup vs baseline: 3.8275x; 2.1249x over previous
#include <cuda_runtime.h>
#include <cuda_fp16.h>
#include <math.h>
#include <stdint.h>

#define B_ 8
#define S_ 1024
#define D_ 1024
#define NH_ 16
#define NKV_ 8
#define HD_ 64
#define M_ (B_*S_)

// ---------------------------------------------------------------------------
// Scratch (allocation-free rule: __device__ globals)
// ---------------------------------------------------------------------------
__device__ float g_q[M_*NH_*HD_];
__device__ float g_k[M_*NKV_*HD_];
__device__ float g_v[M_*NKV_*HD_];

__device__ __half g_xh[M_*D_],  g_xl[M_*D_];            // x hi/lo fp16
__device__ __half g_wqf[D_*D_];                         // weights^T single fp16
__device__ __half g_wkf[(D_/2)*D_];
__device__ __half g_wvf[(D_/2)*D_];
__device__ __half g_wof[D_*D_];
__device__ __half g_qfh[M_*NH_*HD_], g_qfl[M_*NH_*HD_]; // roped q hi/lo (x0.125)
__device__ __half g_kf[M_*NKV_*HD_];                    // roped k single fp16
__device__ __half g_vf[M_*NKV_*HD_];                    // v single fp16
__device__ __half g_aoh[M_*NH_*HD_], g_aol[M_*NH_*HD_]; // attn out hi/lo

// ---------------------------------------------------------------------------
// helpers
// ---------------------------------------------------------------------------
__device__ __forceinline__ uint32_t smem_u32(const void* p) {
    uint32_t a;
    asm("{ .reg .u64 t; cvta.to.shared.u64 t, %1; cvt.u32.u64 %0, t; }" : "=r"(a) : "l"(p));
    return a;
}
__device__ __forceinline__ void ldsm_x4(uint32_t addr, uint32_t* d) {
    asm volatile("ldmatrix.sync.aligned.m8n8.x4.shared.b16 {%0,%1,%2,%3}, [%4];"
                 : "=r"(d[0]), "=r"(d[1]), "=r"(d[2]), "=r"(d[3]) : "r"(addr));
}
__device__ __forceinline__ void ldsm_x4_t(uint32_t addr, uint32_t* d) {
    asm volatile("ldmatrix.sync.aligned.m8n8.x4.trans.shared.b16 {%0,%1,%2,%3}, [%4];"
                 : "=r"(d[0]), "=r"(d[1]), "=r"(d[2]), "=r"(d[3]) : "r"(addr));
}
__device__ __forceinline__ void mma_f16(float* c, const uint32_t* a, const uint32_t* b) {
    asm volatile(
        "mma.sync.aligned.m16n8k16.row.col.f32.f16.f16.f32 "
        "{%0,%1,%2,%3}, {%4,%5,%6,%7}, {%8,%9}, {%0,%1,%2,%3};"
        : "+f"(c[0]), "+f"(c[1]), "+f"(c[2]), "+f"(c[3])
        : "r"(a[0]), "r"(a[1]), "r"(a[2]), "r"(a[3]), "r"(b[0]), "r"(b[1]));
}
__device__ __forceinline__ void cp16(uint32_t dst, const void* src) {
    asm volatile("cp.async.cg.shared.global [%0], [%1], 16;" :: "r"(dst), "l"(src) : "memory");
}
__device__ __forceinline__ void cp_commit() {
    asm volatile("cp.async.commit_group;" ::: "memory");
}
template<int N> __device__ __forceinline__ void cp_wait() {
    asm volatile("cp.async.wait_group %0;" :: "n"(N) : "memory");
}
__device__ __forceinline__ uint32_t pk_h2(float lo, float hi) {
    __half2 t;
    t.x = __float2half_rn(lo);
    t.y = __float2half_rn(hi);
    return *reinterpret_cast<uint32_t*>(&t);
}
__device__ __forceinline__ float h_hi(float x, float* rem) {
    __half h = __float2half_rn(x);
    float hf = __half2float(h);
    *rem = x - hf;
    return hf;
}

// ---------------------------------------------------------------------------
// elementwise: fp32 -> hi/lo fp16
// ---------------------------------------------------------------------------
__global__ void split_h(const float* __restrict__ src,
                        __half* __restrict__ dh,
                        __half* __restrict__ dl, int n4)
{
    int i = blockIdx.x * blockDim.x + threadIdx.x;
    if (i >= n4) return;
    float4 f = *(const float4*)(src + (size_t)i * 4);
    float r0, r1, r2, r3;
    float h0 = h_hi(f.x, &r0), h1 = h_hi(f.y, &r1);
    float h2 = h_hi(f.z, &r2), h3 = h_hi(f.w, &r3);
    *(uint2*)(dh + (size_t)i * 4) = make_uint2(pk_h2(h0, h1), pk_h2(h2, h3));
    *(uint2*)(dl + (size_t)i * 4) = make_uint2(pk_h2(r0, r1), pk_h2(r2, r3));
}

// elementwise: fp32 -> single fp16
__global__ void conv_h(const float* __restrict__ src,
                       __half* __restrict__ df, int n4)
{
    int i = blockIdx.x * blockDim.x + threadIdx.x;
    if (i >= n4) return;
    float4 f = *(const float4*)(src + (size_t)i * 4);
    *(uint2*)(df + (size_t)i * 4) = make_uint2(pk_h2(f.x, f.y), pk_h2(f.z, f.w));
}

// ---------------------------------------------------------------------------
// transpose + single fp16 convert: W[K,N] fp32 -> T[N,K] fp16
// ---------------------------------------------------------------------------
__global__ void trans_conv(const float* __restrict__ W,
                           __half* __restrict__ Tf, int N, int K)
{
    __shared__ float t[32][33];
    const int n0 = blockIdx.x * 32, k0 = blockIdx.y * 32;
    const int tx = threadIdx.x, ty = threadIdx.y;
#pragma unroll
    for (int i = 0; i < 4; i++)
        t[ty + i * 8][tx] = W[(size_t)(k0 + ty + i * 8) * N + n0 + tx];
    __syncthreads();
#pragma unroll
    for (int i = 0; i < 4; i++) {
        size_t o = (size_t)(n0 + ty + i * 8) * K + k0 + tx;
        Tf[o] = __float2half_rn(t[tx][ty + i * 8]);
    }
}

// ---------------------------------------------------------------------------
// HMMA GEMM, fp16 2-pass: C[M,N] = (Ah+Al)[M,K] @ Bf^T[N,K]
// cp.async 2-stage. 128x128 tile, BK=32, 256 thr, 8 warps 2m x 4n.
// dynamic smem: 2 stages x 3 tiles x [128][LDPAD] fp16 = 60KB.
// ---------------------------------------------------------------------------
#define LDPAD 40
#define HG_TILEB (128 * LDPAD * 2)     // 10240
#define HG_STAGEB (3 * HG_TILEB)       // 30720
#define HG_SMEM (2 * HG_STAGEB)        // 61440

__global__ __launch_bounds__(256, 2) void hgemm2(const __half* __restrict__ Ah,
                                                 const __half* __restrict__ Al,
                                                 const __half* __restrict__ Bf,
                                                 float* __restrict__ C,
                                                 int N, int K)
{
    extern __shared__ __align__(16) char dsm[];
    const uint32_t uD = smem_u32(dsm);

    const int tid = threadIdx.x, lane = tid & 31, wid = tid >> 5;
    const int bn = blockIdx.x, bm = blockIdx.y;
    const int warp_m = (wid & 1) * 64;
    const int warp_n = (wid >> 1) * 32;

    const int row  = tid >> 1;
    const int half = tid & 1;
    const __half* pAh = Ah + (size_t)(bm * 128 + row) * K + half * 16;
    const __half* pAl = Al + (size_t)(bm * 128 + row) * K + half * 16;
    const __half* pBf = Bf + (size_t)(bn * 128 + row) * K + half * 16;
    const uint32_t fill_off = (uint32_t)(row * LDPAD + half * 16) * 2;

    const int g = lane >> 3, r = lane & 7;
    uint32_t aoff[4], boff[2];
#pragma unroll
    for (int mt = 0; mt < 4; mt++)
        aoff[mt] = ((warp_m + mt * 16 + (g & 1) * 8 + r) * LDPAD + (g >> 1) * 8) * 2;
#pragma unroll
    for (int nt2 = 0; nt2 < 2; nt2++)
        boff[nt2] = ((warp_n + nt2 * 16 + (g >> 1) * 8 + r) * LDPAD + (g & 1) * 8) * 2;

    float acc[4][4][4];
#pragma unroll
    for (int i = 0; i < 4; i++)
#pragma unroll
        for (int j = 0; j < 4; j++)
#pragma unroll
            for (int t = 0; t < 4; t++) acc[i][j][t] = 0.f;

    const int NCH = K / 32;

    // prologue: stage 0
    {
        const uint32_t d = uD + fill_off;
        cp16(d,                pAh); cp16(d + 16,                pAh + 8);
        cp16(d + HG_TILEB,     pAl); cp16(d + HG_TILEB + 16,     pAl + 8);
        cp16(d + 2 * HG_TILEB, pBf); cp16(d + 2 * HG_TILEB + 16, pBf + 8);
        cp_commit();
    }

    for (int ch = 0; ch < NCH; ch++) {
        if (ch + 1 < NCH) {
            const int k1 = (ch + 1) * 32;
            const uint32_t d = uD + ((ch + 1) & 1) * HG_STAGEB + fill_off;
            cp16(d,                pAh + k1); cp16(d + 16,                pAh + k1 + 8);
            cp16(d + HG_TILEB,     pAl + k1); cp16(d + HG_TILEB + 16,     pAl + k1 + 8);
            cp16(d + 2 * HG_TILEB, pBf + k1); cp16(d + 2 * HG_TILEB + 16, pBf + k1 + 8);
            cp_commit();
            cp_wait<1>();
        } else {
            cp_wait<0>();
        }
        __syncthreads();

        const uint32_t uSt = uD + (ch & 1) * HG_STAGEB;
        const uint32_t uAh = uSt, uAl = uSt + HG_TILEB, uBf = uSt + 2 * HG_TILEB;
#pragma unroll
        for (int ks = 0; ks < 2; ks++) {
            const uint32_t kadd = ks * 32;
            uint32_t bfr[2][4], afr[4][4];
#pragma unroll
            for (int nt2 = 0; nt2 < 2; nt2++) ldsm_x4(uBf + boff[nt2] + kadd, bfr[nt2]);
            // pass 1: Ah
#pragma unroll
            for (int mt = 0; mt < 4; mt++) ldsm_x4(uAh + aoff[mt] + kadd, afr[mt]);
#pragma unroll
            for (int mt = 0; mt < 4; mt++)
#pragma unroll
                for (int nt = 0; nt < 4; nt++)
                    mma_f16(acc[mt][nt], afr[mt], bfr[nt >> 1] + (nt & 1) * 2);
            // pass 2: Al (reuse bfr)
#pragma unroll
            for (int mt = 0; mt < 4; mt++) ldsm_x4(uAl + aoff[mt] + kadd, afr[mt]);
#pragma unroll
            for (int mt = 0; mt < 4; mt++)
#pragma unroll
                for (int nt = 0; nt < 4; nt++)
                    mma_f16(acc[mt][nt], afr[mt], bfr[nt >> 1] + (nt & 1) * 2);
        }
        __syncthreads();
    }

    const int erow = lane >> 2;
    const int ecol = (lane & 3) * 2;
#pragma unroll
    for (int mt = 0; mt < 4; mt++) {
#pragma unroll
        for (int nt = 0; nt < 4; nt++) {
            float* Cr = C + (size_t)(bm * 128 + warp_m + mt * 16 + erow) * N
                          + bn * 128 + warp_n + nt * 8 + ecol;
            *(float2*)Cr                   = make_float2(acc[mt][nt][0], acc[mt][nt][1]);
            *(float2*)(Cr + 8 * (size_t)N) = make_float2(acc[mt][nt][2], acc[mt][nt][3]);
        }
    }
}

// ---------------------------------------------------------------------------
// RoPE + scale -> hi/lo fp16
// ---------------------------------------------------------------------------
__global__ void rope_split_h(const float* __restrict__ x,
                             __half* __restrict__ oh,
                             __half* __restrict__ ol,
                             const float* __restrict__ cs,
                             const float* __restrict__ sn,
                             int nh, float scale, int total_pairs)
{
    int p = blockIdx.x * blockDim.x + threadIdx.x;
    if (p >= total_pairs) return;
    int d2 = p & 31;
    int s  = (p / (32 * nh)) & (S_ - 1);
    float c  = cs[s * 32 + d2];
    float si = sn[s * 32 + d2];
    float2 xv = *(const float2*)(x + (size_t)p * 2);
    float rx = (xv.x * c - xv.y * si) * scale;
    float ry = (xv.x * si + xv.y * c) * scale;
    float l0, l1;
    float h0 = h_hi(rx, &l0), h1 = h_hi(ry, &l1);
    *(uint32_t*)(oh + (size_t)p * 2) = pk_h2(h0, h1);
    *(uint32_t*)(ol + (size_t)p * 2) = pk_h2(l0, l1);
}

// RoPE -> single fp16
__global__ void rope_conv_h(const float* __restrict__ x,
                            __half* __restrict__ of,
                            const float* __restrict__ cs,
                            const float* __restrict__ sn,
                            int nh, int total_pairs)
{
    int p = blockIdx.x * blockDim.x + threadIdx.x;
    if (p >= total_pairs) return;
    int d2 = p & 31;
    int s  = (p / (32 * nh)) & (S_ - 1);
    float c  = cs[s * 32 + d2];
    float si = sn[s * 32 + d2];
    float2 xv = *(const float2*)(x + (size_t)p * 2);
    float rx = xv.x * c - xv.y * si;
    float ry = xv.x * si + xv.y * c;
    *(uint32_t*)(of + (size_t)p * 2) = pk_h2(rx, ry);
}

// ---------------------------------------------------------------------------
// HMMA flash attention, fp16 2-pass (Q and P split hi/lo; K,V single fp16).
// cp.async 2-stage K/V pipeline. Q staged once in smem (reused region).
// dynamic smem: max(Q hi+lo [128][72]x2 = 36KB, 2 stages x {K,V} = 36KB).
// ---------------------------------------------------------------------------
#define APAD 72
#define TILE_E (64 * APAD)
#define AT_TILEB (TILE_E * 2)          // 9216 (64-row fp16 tile)
#define AT_STAGEB (2 * AT_TILEB)       // 18432 (Kf + Vf)
#define AT_SMEM (2 * AT_STAGEB)        // 36864

__global__ __launch_bounds__(256) void attn_mma2(const __half* __restrict__ qh,
                                                 const __half* __restrict__ ql,
                                                 const __half* __restrict__ kf,
                                                 const __half* __restrict__ vf,
                                                 __half* __restrict__ aoh,
                                                 __half* __restrict__ aol)
{
    extern __shared__ __align__(16) char dsm[];
    __half* sm = (__half*)dsm;
    const uint32_t uD = smem_u32(dsm);

    const int tid = threadIdx.x, lane = tid & 31, wid = tid >> 5;
    const int qt = blockIdx.x, h = blockIdx.y, b = blockIdx.z;
    const int kvh = h >> 1;
    const int lg = lane >> 3, lr = lane & 7;
    const int quad = lane >> 2, qd = lane & 3;

    // ---- Q stage (Qh at 0, Ql at +18432; uses both stage regions) ----
    {
        const int row = tid >> 1, half = tid & 1;
        const size_t gq = (((size_t)(b * S_ + qt * 128 + row)) * NH_ + h) * HD_ + half * 32;
        __half* dh = sm + row * APAD + half * 32;
        __half* dl = sm + AT_STAGEB / 2 + row * APAD + half * 32;   // +9216 halves = +18432B
#pragma unroll
        for (int i = 0; i < 4; i++) *(uint4*)(dh + i * 8) = *(const uint4*)(qh + gq + i * 8);
#pragma unroll
        for (int i = 0; i < 4; i++) *(uint4*)(dl + i * 8) = *(const uint4*)(ql + gq + i * 8);
    }
    __syncthreads();

    uint32_t qfh[4][4], qfl[4][4];
    {
        const int rowa = wid * 16 + (lg & 1) * 8 + lr;
#pragma unroll
        for (int kc = 0; kc < 4; kc++) {
            const uint32_t off = (uint32_t)(rowa * APAD + (lg >> 1) * 8 + kc * 16) * 2;
            ldsm_x4(uD + off, qfh[kc]);
            ldsm_x4(uD + AT_STAGEB + off, qfl[kc]);
        }
    }
    __syncthreads();   // Q reads done before cp.async overwrites

    float o[8][4];
#pragma unroll
    for (int t = 0; t < 8; t++)
#pragma unroll
        for (int j = 0; j < 4; j++) o[t][j] = 0.f;
    float m0 = -1e30f, m1 = -1e30f, l0 = 0.f, l1 = 0.f;

    const int qbaseG = qt * 128 + wid * 16;
    const int lim0 = (qbaseG + quad) | 7;
    const int lim1 = (qbaseG + quad + 8) | 7;
    const int ntiles = 2 * qt + 2;

    const int krow = tid >> 2, kc4 = (tid & 3) * 16;
    const uint32_t fill_off = (uint32_t)(krow * APAD + kc4) * 2;

    // prologue: tile 0 -> stage 0
    {
        const size_t gkv = (((size_t)(b * S_ + krow)) * NKV_ + kvh) * HD_ + kc4;
        const uint32_t d = uD + fill_off;
        cp16(d,            kf + gkv); cp16(d + 16,            kf + gkv + 8);
        cp16(d + AT_TILEB, vf + gkv); cp16(d + AT_TILEB + 16, vf + gkv + 8);
        cp_commit();
    }

    for (int kt = 0; kt < ntiles; kt++) {
        if (kt + 1 < ntiles) {
            const size_t gkv = (((size_t)(b * S_ + (kt + 1) * 64 + krow)) * NKV_ + kvh) * HD_ + kc4;
            const uint32_t d = uD + ((kt + 1) & 1) * AT_STAGEB + fill_off;
            cp16(d,            kf + gkv); cp16(d + 16,            kf + gkv + 8);
            cp16(d + AT_TILEB, vf + gkv); cp16(d + AT_TILEB + 16, vf + gkv + 8);
            cp_commit();
            cp_wait<1>();
        } else {
            cp_wait<0>();
        }
        __syncthreads();

        if (kt * 64 <= qbaseG + 15) {
            const uint32_t uSt = uD + (kt & 1) * AT_STAGEB;
            const uint32_t uKf = uSt, uVf = uSt + AT_TILEB;

            // ---- S = (Qh+Ql) @ K^T ----
            float s[8][4];
#pragma unroll
            for (int t = 0; t < 8; t++)
#pragma unroll
                for (int j = 0; j < 4; j++) s[t][j] = 0.f;

#pragma unroll
            for (int kc = 0; kc < 4; kc++) {
#pragma unroll
                for (int nt2 = 0; nt2 < 4; nt2++) {
                    const uint32_t boff =
                        (uint32_t)((nt2 * 16 + (lg >> 1) * 8 + lr) * APAD + (lg & 1) * 8 + kc * 16) * 2;
                    uint32_t f[4];
                    ldsm_x4(uKf + boff, f);
                    mma_f16(s[nt2 * 2],     qfh[kc], f);
                    mma_f16(s[nt2 * 2 + 1], qfh[kc], f + 2);
                    mma_f16(s[nt2 * 2],     qfl[kc], f);
                    mma_f16(s[nt2 * 2 + 1], qfl[kc], f + 2);
                }
            }

            // ---- block-causal mask ----
            if (kt * 64 + 63 > qbaseG + 7) {
#pragma unroll
                for (int t = 0; t < 8; t++) {
                    const int key = kt * 64 + t * 8 + qd * 2;
                    if (key     > lim0) s[t][0] = -1e30f;
                    if (key + 1 > lim0) s[t][1] = -1e30f;
                    if (key     > lim1) s[t][2] = -1e30f;
                    if (key + 1 > lim1) s[t][3] = -1e30f;
                }
            }

            // ---- online softmax ----
            float mx0 = -1e30f, mx1 = -1e30f;
#pragma unroll
            for (int t = 0; t < 8; t++) {
                mx0 = fmaxf(mx0, fmaxf(s[t][0], s[t][1]));
                mx1 = fmaxf(mx1, fmaxf(s[t][2], s[t][3]));
            }
            mx0 = fmaxf(mx0, __shfl_xor_sync(0xffffffffu, mx0, 1));
            mx0 = fmaxf(mx0, __shfl_xor_sync(0xffffffffu, mx0, 2));
            mx1 = fmaxf(mx1, __shfl_xor_sync(0xffffffffu, mx1, 1));
            mx1 = fmaxf(mx1, __shfl_xor_sync(0xffffffffu, mx1, 2));

            const float mn0 = fmaxf(m0, mx0), mn1 = fmaxf(m1, mx1);
            const float a0 = __expf(m0 - mn0), a1 = __expf(m1 - mn1);
            l0 *= a0; l1 *= a1;
#pragma unroll
            for (int t = 0; t < 8; t++) {
                o[t][0] *= a0; o[t][1] *= a0; o[t][2] *= a1; o[t][3] *= a1;
            }
            float sl0 = 0.f, sl1 = 0.f;
#pragma unroll
            for (int t = 0; t < 8; t++) {
                s[t][0] = __expf(s[t][0] - mn0); s[t][1] = __expf(s[t][1] - mn0);
                s[t][2] = __expf(s[t][2] - mn1); s[t][3] = __expf(s[t][3] - mn1);
                sl0 += s[t][0] + s[t][1];
                sl1 += s[t][2] + s[t][3];
            }
            sl0 += __shfl_xor_sync(0xffffffffu, sl0, 1);
            sl0 += __shfl_xor_sync(0xffffffffu, sl0, 2);
            sl1 += __shfl_xor_sync(0xffffffffu, sl1, 1);
            sl1 += __shfl_xor_sync(0xffffffffu, sl1, 2);
            l0 += sl0; l1 += sl1;
            m0 = mn0; m1 = mn1;

            // ---- pack P hi/lo fp16 A-fragments ----
            uint32_t ph[8][2], pl[8][2];
#pragma unroll
            for (int t = 0; t < 8; t++) {
                float r0, r1, r2, r3;
                float h0 = h_hi(s[t][0], &r0), h1 = h_hi(s[t][1], &r1);
                float h2 = h_hi(s[t][2], &r2), h3 = h_hi(s[t][3], &r3);
                ph[t][0] = pk_h2(h0, h1); ph[t][1] = pk_h2(h2, h3);
                pl[t][0] = pk_h2(r0, r1); pl[t][1] = pk_h2(r2, r3);
            }

            // ---- O += (Ph+Pl) @ V ----
#pragma unroll
            for (int kc = 0; kc < 4; kc++) {
                uint32_t ah[4] = {ph[2*kc][0], ph[2*kc][1], ph[2*kc+1][0], ph[2*kc+1][1]};
                uint32_t al[4] = {pl[2*kc][0], pl[2*kc][1], pl[2*kc+1][0], pl[2*kc+1][1]};
#pragma unroll
                for (int nt2 = 0; nt2 < 4; nt2++) {
                    const uint32_t voff =
                        (uint32_t)((kc * 16 + (lg & 1) * 8 + lr) * APAD + nt2 * 16 + (lg >> 1) * 8) * 2;
                    uint32_t f[4];
                    ldsm_x4_t(uVf + voff, f);
                    mma_f16(o[nt2 * 2],     ah, f);
                    mma_f16(o[nt2 * 2 + 1], ah, f + 2);
                    mma_f16(o[nt2 * 2],     al, f);
                    mma_f16(o[nt2 * 2 + 1], al, f + 2);
                }
            }
        }
        __syncthreads();
    }

    // ---- epilogue: normalize + hi/lo fp16 split write ----
    const float inv0 = 1.f / l0, inv1 = 1.f / l1;
    const int row0 = qbaseG + quad;
    const size_t e0 = (((size_t)(b * S_ + row0)) * NH_ + h) * HD_ + qd * 2;
    const size_t e1 = (((size_t)(b * S_ + row0 + 8)) * NH_ + h) * HD_ + qd * 2;
#pragma unroll
    for (int t = 0; t < 8; t++) {
        float x0 = o[t][0] * inv0, x1 = o[t][1] * inv0;
        float y0 = o[t][2] * inv1, y1 = o[t][3] * inv1;
        float rx0, rx1, ry0, ry1;
        float hx0 = h_hi(x0, &rx0), hx1 = h_hi(x1, &rx1);
        float hy0 = h_hi(y0, &ry0), hy1 = h_hi(y1, &ry1);
        *(uint32_t*)(aoh + e0 + t * 8) = pk_h2(hx0, hx1);
        *(uint32_t*)(aol + e0 + t * 8) = pk_h2(rx0, rx1);
        *(uint32_t*)(aoh + e1 + t * 8) = pk_h2(hy0, hy1);
        *(uint32_t*)(aol + e1 + t * 8) = pk_h2(ry0, ry1);
    }
}

// ---------------------------------------------------------------------------
extern "C" void kernel_launch(void* const* d_in, const int* in_sizes, int n_in,
                              void* d_out, int out_size)
{
    const float* x   = (const float*)d_in[0];
    const float* wq  = (const float*)d_in[1];
    const float* wk  = (const float*)d_in[2];
    const float* wv  = (const float*)d_in[3];
    const float* wo  = (const float*)d_in[4];
    const float* fcc = (const float*)d_in[5];
    const float* fcs = (const float*)d_in[6];
    (void)in_sizes; (void)n_in;

    float *q, *k, *v;
    __half *xh, *xl, *wqf, *wkf, *wvf, *wof;
    __half *qfh, *qfl, *kf, *vf, *aoh, *aol;
    cudaGetSymbolAddress((void**)&q,   g_q);
    cudaGetSymbolAddress((void**)&k,   g_k);
    cudaGetSymbolAddress((void**)&v,   g_v);
    cudaGetSymbolAddress((void**)&xh,  g_xh);
    cudaGetSymbolAddress((void**)&xl,  g_xl);
    cudaGetSymbolAddress((void**)&wqf, g_wqf);
    cudaGetSymbolAddress((void**)&wkf, g_wkf);
    cudaGetSymbolAddress((void**)&wvf, g_wvf);
    cudaGetSymbolAddress((void**)&wof, g_wof);
    cudaGetSymbolAddress((void**)&qfh, g_qfh);
    cudaGetSymbolAddress((void**)&qfl, g_qfl);
    cudaGetSymbolAddress((void**)&kf,  g_kf);
    cudaGetSymbolAddress((void**)&vf,  g_vf);
    cudaGetSymbolAddress((void**)&aoh, g_aoh);
    cudaGetSymbolAddress((void**)&aol, g_aol);

    cudaFuncSetAttribute(hgemm2,    cudaFuncAttributeMaxDynamicSharedMemorySize, HG_SMEM);
    cudaFuncSetAttribute(attn_mma2, cudaFuncAttributeMaxDynamicSharedMemorySize, AT_SMEM);

    const int M = M_;   // 8192

    // input prep
    split_h<<<(M * D_ / 4 + 255) / 256, 256>>>(x, xh, xl, M * D_ / 4);
    trans_conv<<<dim3(D_/32, D_/32), dim3(32, 8)>>>(wq, wqf, D_,   D_);
    trans_conv<<<dim3(D_/64, D_/32), dim3(32, 8)>>>(wk, wkf, D_/2, D_);
    trans_conv<<<dim3(D_/64, D_/32), dim3(32, 8)>>>(wv, wvf, D_/2, D_);
    trans_conv<<<dim3(D_/32, D_/32), dim3(32, 8)>>>(wo, wof, D_,   D_);

    // QKV projections (fp16 2-pass)
    hgemm2<<<dim3(NH_*HD_/128,  M/128), 256, HG_SMEM>>>(xh, xl, wqf, q, NH_*HD_,  D_);
    hgemm2<<<dim3(NKV_*HD_/128, M/128), 256, HG_SMEM>>>(xh, xl, wkf, k, NKV_*HD_, D_);
    hgemm2<<<dim3(NKV_*HD_/128, M/128), 256, HG_SMEM>>>(xh, xl, wvf, v, NKV_*HD_, D_);

    // RoPE: q -> hi/lo (x0.125), k -> single fp16; v -> single fp16
    {
        int qp = M * NH_ * (HD_ / 2);
        int kp = M * NKV_ * (HD_ / 2);
        rope_split_h<<<(qp + 255) / 256, 256>>>(q, qfh, qfl, fcc, fcs, NH_, 0.125f, qp);
        rope_conv_h<<<(kp + 255) / 256, 256>>>(k, kf, fcc, fcs, NKV_, kp);
        conv_h<<<(M * NKV_ * HD_ / 4 + 255) / 256, 256>>>(v, vf, M * NKV_ * HD_ / 4);
    }

    // Attention (fp16 2-pass)
    attn_mma2<<<dim3(S_/128, NH_, B_), 256, AT_SMEM>>>(qfh, qfl, kf, vf, aoh, aol);

    // Output projection (fp16 2-pass)
    hgemm2<<<dim3(D_/128, M/128), 256, HG_SMEM>>>(aoh, aol, wof, (float*)d_out, D_, D_);
    (void)out_size;
}

// round 15
// speedup vs baseline: 4.0315x; 1.0533x over previous
#include <cuda_runtime.h>
#include <cuda_fp16.h>
#include <math.h>
#include <stdint.h>

#define B_ 8
#define S_ 1024
#define D_ 1024
#define NH_ 16
#define NKV_ 8
#define HD_ 64
#define M_ (B_*S_)

// ---------------------------------------------------------------------------
// Scratch (allocation-free rule: __device__ globals)
// ---------------------------------------------------------------------------
__device__ __half g_xh[M_*D_],  g_xl[M_*D_];            // x hi/lo fp16
__device__ __half g_wqf[D_*D_];                         // weights^T single fp16
__device__ __half g_wkf[(D_/2)*D_];
__device__ __half g_wvf[(D_/2)*D_];
__device__ __half g_wof[D_*D_];
__device__ __half g_qfh[M_*NH_*HD_], g_qfl[M_*NH_*HD_]; // roped q hi/lo (x0.125)
__device__ __half g_kf[M_*NKV_*HD_];                    // roped k single fp16
__device__ __half g_vf[M_*NKV_*HD_];                    // v single fp16
__device__ __half g_aoh[M_*NH_*HD_], g_aol[M_*NH_*HD_]; // attn out hi/lo

// ---------------------------------------------------------------------------
// helpers
// ---------------------------------------------------------------------------
__device__ __forceinline__ uint32_t smem_u32(const void* p) {
    uint32_t a;
    asm("{ .reg .u64 t; cvta.to.shared.u64 t, %1; cvt.u32.u64 %0, t; }" : "=r"(a) : "l"(p));
    return a;
}
__device__ __forceinline__ void ldsm_x4(uint32_t addr, uint32_t* d) {
    asm volatile("ldmatrix.sync.aligned.m8n8.x4.shared.b16 {%0,%1,%2,%3}, [%4];"
                 : "=r"(d[0]), "=r"(d[1]), "=r"(d[2]), "=r"(d[3]) : "r"(addr));
}
__device__ __forceinline__ void ldsm_x4_t(uint32_t addr, uint32_t* d) {
    asm volatile("ldmatrix.sync.aligned.m8n8.x4.trans.shared.b16 {%0,%1,%2,%3}, [%4];"
                 : "=r"(d[0]), "=r"(d[1]), "=r"(d[2]), "=r"(d[3]) : "r"(addr));
}
__device__ __forceinline__ void mma_f16(float* c, const uint32_t* a, const uint32_t* b) {
    asm volatile(
        "mma.sync.aligned.m16n8k16.row.col.f32.f16.f16.f32 "
        "{%0,%1,%2,%3}, {%4,%5,%6,%7}, {%8,%9}, {%0,%1,%2,%3};"
        : "+f"(c[0]), "+f"(c[1]), "+f"(c[2]), "+f"(c[3])
        : "r"(a[0]), "r"(a[1]), "r"(a[2]), "r"(a[3]), "r"(b[0]), "r"(b[1]));
}
__device__ __forceinline__ void cp16(uint32_t dst, const void* src) {
    asm volatile("cp.async.cg.shared.global [%0], [%1], 16;" :: "r"(dst), "l"(src) : "memory");
}
__device__ __forceinline__ void cp_commit() {
    asm volatile("cp.async.commit_group;" ::: "memory");
}
template<int N> __device__ __forceinline__ void cp_wait() {
    asm volatile("cp.async.wait_group %0;" :: "n"(N) : "memory");
}
__device__ __forceinline__ uint32_t pk_h2(float lo, float hi) {
    __half2 t;
    t.x = __float2half_rn(lo);
    t.y = __float2half_rn(hi);
    return *reinterpret_cast<uint32_t*>(&t);
}
__device__ __forceinline__ float h_hi(float x, float* rem) {
    __half h = __float2half_rn(x);
    float hf = __half2float(h);
    *rem = x - hf;
    return hf;
}

// ---------------------------------------------------------------------------
// elementwise: fp32 -> hi/lo fp16 (for x)
// ---------------------------------------------------------------------------
__global__ void split_h(const float* __restrict__ src,
                        __half* __restrict__ dh,
                        __half* __restrict__ dl, int n4)
{
    int i = blockIdx.x * blockDim.x + threadIdx.x;
    if (i >= n4) return;
    float4 f = *(const float4*)(src + (size_t)i * 4);
    float r0, r1, r2, r3;
    float h0 = h_hi(f.x, &r0), h1 = h_hi(f.y, &r1);
    float h2 = h_hi(f.z, &r2), h3 = h_hi(f.w, &r3);
    *(uint2*)(dh + (size_t)i * 4) = make_uint2(pk_h2(h0, h1), pk_h2(h2, h3));
    *(uint2*)(dl + (size_t)i * 4) = make_uint2(pk_h2(r0, r1), pk_h2(r2, r3));
}

// ---------------------------------------------------------------------------
// transpose + single fp16 convert: W[K,N] fp32 -> T[N,K] fp16
// ---------------------------------------------------------------------------
__global__ void trans_conv(const float* __restrict__ W,
                           __half* __restrict__ Tf, int N, int K)
{
    __shared__ float t[32][33];
    const int n0 = blockIdx.x * 32, k0 = blockIdx.y * 32;
    const int tx = threadIdx.x, ty = threadIdx.y;
#pragma unroll
    for (int i = 0; i < 4; i++)
        t[ty + i * 8][tx] = W[(size_t)(k0 + ty + i * 8) * N + n0 + tx];
    __syncthreads();
#pragma unroll
    for (int i = 0; i < 4; i++) {
        size_t o = (size_t)(n0 + ty + i * 8) * K + k0 + tx;
        Tf[o] = __float2half_rn(t[tx][ty + i * 8]);
    }
}

// ---------------------------------------------------------------------------
// HMMA GEMM, fp16 2-pass A (Ah+Al) x single-fp16 B, cp.async 2-stage.
// Epilogue modes:
//   0: fp32 C                      (output projection)
//   1: RoPE + scale + hi/lo fp16   (q projection)
//   2: RoPE + single fp16          (k projection)
//   3: single fp16                 (v projection)
// RoPE uses the fact that each C-fragment thread holds adjacent even/odd
// columns (ecol = (lane&3)*2) = exactly one rope pair within the 64-col head.
// ---------------------------------------------------------------------------
#define LDPAD 40
#define HG_TILEB (128 * LDPAD * 2)     // 10240
#define HG_STAGEB (3 * HG_TILEB)       // 30720
#define HG_SMEM (2 * HG_STAGEB)        // 61440

__global__ __launch_bounds__(256, 2) void hgemm2(const __half* __restrict__ Ah,
                                                 const __half* __restrict__ Al,
                                                 const __half* __restrict__ Bf,
                                                 float* __restrict__ C32,
                                                 __half* __restrict__ Ch,
                                                 __half* __restrict__ Cl,
                                                 const float* __restrict__ cs,
                                                 const float* __restrict__ sn,
                                                 int N, int K, int mode, float scale)
{
    extern __shared__ __align__(16) char dsm[];
    const uint32_t uD = smem_u32(dsm);

    const int tid = threadIdx.x, lane = tid & 31, wid = tid >> 5;
    const int bn = blockIdx.x, bm = blockIdx.y;
    const int warp_m = (wid & 1) * 64;
    const int warp_n = (wid >> 1) * 32;

    const int row  = tid >> 1;
    const int half = tid & 1;
    const __half* pAh = Ah + (size_t)(bm * 128 + row) * K + half * 16;
    const __half* pAl = Al + (size_t)(bm * 128 + row) * K + half * 16;
    const __half* pBf = Bf + (size_t)(bn * 128 + row) * K + half * 16;
    const uint32_t fill_off = (uint32_t)(row * LDPAD + half * 16) * 2;

    const int g = lane >> 3, r = lane & 7;
    uint32_t aoff[4], boff[2];
#pragma unroll
    for (int mt = 0; mt < 4; mt++)
        aoff[mt] = ((warp_m + mt * 16 + (g & 1) * 8 + r) * LDPAD + (g >> 1) * 8) * 2;
#pragma unroll
    for (int nt2 = 0; nt2 < 2; nt2++)
        boff[nt2] = ((warp_n + nt2 * 16 + (g >> 1) * 8 + r) * LDPAD + (g & 1) * 8) * 2;

    float acc[4][4][4];
#pragma unroll
    for (int i = 0; i < 4; i++)
#pragma unroll
        for (int j = 0; j < 4; j++)
#pragma unroll
            for (int t = 0; t < 4; t++) acc[i][j][t] = 0.f;

    const int NCH = K / 32;

    // prologue: stage 0
    {
        const uint32_t d = uD + fill_off;
        cp16(d,                pAh); cp16(d + 16,                pAh + 8);
        cp16(d + HG_TILEB,     pAl); cp16(d + HG_TILEB + 16,     pAl + 8);
        cp16(d + 2 * HG_TILEB, pBf); cp16(d + 2 * HG_TILEB + 16, pBf + 8);
        cp_commit();
    }

    for (int ch = 0; ch < NCH; ch++) {
        if (ch + 1 < NCH) {
            const int k1 = (ch + 1) * 32;
            const uint32_t d = uD + ((ch + 1) & 1) * HG_STAGEB + fill_off;
            cp16(d,                pAh + k1); cp16(d + 16,                pAh + k1 + 8);
            cp16(d + HG_TILEB,     pAl + k1); cp16(d + HG_TILEB + 16,     pAl + k1 + 8);
            cp16(d + 2 * HG_TILEB, pBf + k1); cp16(d + 2 * HG_TILEB + 16, pBf + k1 + 8);
            cp_commit();
            cp_wait<1>();
        } else {
            cp_wait<0>();
        }
        __syncthreads();

        const uint32_t uSt = uD + (ch & 1) * HG_STAGEB;
        const uint32_t uAh = uSt, uAl = uSt + HG_TILEB, uBf = uSt + 2 * HG_TILEB;
#pragma unroll
        for (int ks = 0; ks < 2; ks++) {
            const uint32_t kadd = ks * 32;
            uint32_t bfr[2][4], afr[4][4];
#pragma unroll
            for (int nt2 = 0; nt2 < 2; nt2++) ldsm_x4(uBf + boff[nt2] + kadd, bfr[nt2]);
#pragma unroll
            for (int mt = 0; mt < 4; mt++) ldsm_x4(uAh + aoff[mt] + kadd, afr[mt]);
#pragma unroll
            for (int mt = 0; mt < 4; mt++)
#pragma unroll
                for (int nt = 0; nt < 4; nt++)
                    mma_f16(acc[mt][nt], afr[mt], bfr[nt >> 1] + (nt & 1) * 2);
#pragma unroll
            for (int mt = 0; mt < 4; mt++) ldsm_x4(uAl + aoff[mt] + kadd, afr[mt]);
#pragma unroll
            for (int mt = 0; mt < 4; mt++)
#pragma unroll
                for (int nt = 0; nt < 4; nt++)
                    mma_f16(acc[mt][nt], afr[mt], bfr[nt >> 1] + (nt & 1) * 2);
        }
        __syncthreads();
    }

    // ---- epilogue ----
    const int erow = lane >> 2;
    const int ecol = (lane & 3) * 2;
#pragma unroll
    for (int mt = 0; mt < 4; mt++) {
#pragma unroll
        for (int nt = 0; nt < 4; nt++) {
            const int gr = bm * 128 + warp_m + mt * 16 + erow;   // global row (b*S+s)
            const int gc = bn * 128 + warp_n + nt * 8 + ecol;    // even column
            float a0 = acc[mt][nt][0], a1 = acc[mt][nt][1];
            float a2 = acc[mt][nt][2], a3 = acc[mt][nt][3];
            if (mode == 0) {
                float* Cr = C32 + (size_t)gr * N + gc;
                *(float2*)Cr                   = make_float2(a0, a1);
                *(float2*)(Cr + 8 * (size_t)N) = make_float2(a2, a3);
            } else if (mode == 3) {
                *(uint32_t*)(Ch + (size_t)gr * N + gc)       = pk_h2(a0, a1);
                *(uint32_t*)(Ch + (size_t)(gr + 8) * N + gc) = pk_h2(a2, a3);
            } else {
                const int d2 = (gc & 63) >> 1;
                const int s0 = gr & (S_ - 1), s1 = (gr + 8) & (S_ - 1);
                const float c0 = cs[s0 * 32 + d2], t0 = sn[s0 * 32 + d2];
                const float c1 = cs[s1 * 32 + d2], t1 = sn[s1 * 32 + d2];
                float r0 = (a0 * c0 - a1 * t0) * scale;
                float r1 = (a0 * t0 + a1 * c0) * scale;
                float r2 = (a2 * c1 - a3 * t1) * scale;
                float r3 = (a2 * t1 + a3 * c1) * scale;
                if (mode == 2) {
                    *(uint32_t*)(Ch + (size_t)gr * N + gc)       = pk_h2(r0, r1);
                    *(uint32_t*)(Ch + (size_t)(gr + 8) * N + gc) = pk_h2(r2, r3);
                } else {
                    float l0, l1, l2, l3;
                    float h0 = h_hi(r0, &l0), h1 = h_hi(r1, &l1);
                    float h2 = h_hi(r2, &l2), h3 = h_hi(r3, &l3);
                    *(uint32_t*)(Ch + (size_t)gr * N + gc)       = pk_h2(h0, h1);
                    *(uint32_t*)(Cl + (size_t)gr * N + gc)       = pk_h2(l0, l1);
                    *(uint32_t*)(Ch + (size_t)(gr + 8) * N + gc) = pk_h2(h2, h3);
                    *(uint32_t*)(Cl + (size_t)(gr + 8) * N + gc) = pk_h2(l2, l3);
                }
            }
        }
    }
}

// ---------------------------------------------------------------------------
// HMMA flash attention, fp16: Q 2-pass (hi/lo); K,V,P single fp16.
// cp.async 2-stage K/V pipeline; Q staged once.
// ---------------------------------------------------------------------------
#define APAD 72
#define TILE_E (64 * APAD)
#define AT_TILEB (TILE_E * 2)          // 9216
#define AT_STAGEB (2 * AT_TILEB)       // 18432
#define AT_SMEM (2 * AT_STAGEB)        // 36864

__global__ __launch_bounds__(256) void attn_mma2(const __half* __restrict__ qh,
                                                 const __half* __restrict__ ql,
                                                 const __half* __restrict__ kf,
                                                 const __half* __restrict__ vf,
                                                 __half* __restrict__ aoh,
                                                 __half* __restrict__ aol)
{
    extern __shared__ __align__(16) char dsm[];
    __half* sm = (__half*)dsm;
    const uint32_t uD = smem_u32(dsm);

    const int tid = threadIdx.x, lane = tid & 31, wid = tid >> 5;
    const int qt = blockIdx.x, h = blockIdx.y, b = blockIdx.z;
    const int kvh = h >> 1;
    const int lg = lane >> 3, lr = lane & 7;
    const int quad = lane >> 2, qd = lane & 3;

    // ---- Q stage ----
    {
        const int row = tid >> 1, half = tid & 1;
        const size_t gq = (((size_t)(b * S_ + qt * 128 + row)) * NH_ + h) * HD_ + half * 32;
        __half* dh = sm + row * APAD + half * 32;
        __half* dl = sm + AT_STAGEB / 2 + row * APAD + half * 32;
#pragma unroll
        for (int i = 0; i < 4; i++) *(uint4*)(dh + i * 8) = *(const uint4*)(qh + gq + i * 8);
#pragma unroll
        for (int i = 0; i < 4; i++) *(uint4*)(dl + i * 8) = *(const uint4*)(ql + gq + i * 8);
    }
    __syncthreads();

    uint32_t qfh[4][4], qfl[4][4];
    {
        const int rowa = wid * 16 + (lg & 1) * 8 + lr;
#pragma unroll
        for (int kc = 0; kc < 4; kc++) {
            const uint32_t off = (uint32_t)(rowa * APAD + (lg >> 1) * 8 + kc * 16) * 2;
            ldsm_x4(uD + off, qfh[kc]);
            ldsm_x4(uD + AT_STAGEB + off, qfl[kc]);
        }
    }
    __syncthreads();

    float o[8][4];
#pragma unroll
    for (int t = 0; t < 8; t++)
#pragma unroll
        for (int j = 0; j < 4; j++) o[t][j] = 0.f;
    float m0 = -1e30f, m1 = -1e30f, l0 = 0.f, l1 = 0.f;

    const int qbaseG = qt * 128 + wid * 16;
    const int lim0 = (qbaseG + quad) | 7;
    const int lim1 = (qbaseG + quad + 8) | 7;
    const int ntiles = 2 * qt + 2;

    const int krow = tid >> 2, kc4 = (tid & 3) * 16;
    const uint32_t fill_off = (uint32_t)(krow * APAD + kc4) * 2;

    {
        const size_t gkv = (((size_t)(b * S_ + krow)) * NKV_ + kvh) * HD_ + kc4;
        const uint32_t d = uD + fill_off;
        cp16(d,            kf + gkv); cp16(d + 16,            kf + gkv + 8);
        cp16(d + AT_TILEB, vf + gkv); cp16(d + AT_TILEB + 16, vf + gkv + 8);
        cp_commit();
    }

    for (int kt = 0; kt < ntiles; kt++) {
        if (kt + 1 < ntiles) {
            const size_t gkv = (((size_t)(b * S_ + (kt + 1) * 64 + krow)) * NKV_ + kvh) * HD_ + kc4;
            const uint32_t d = uD + ((kt + 1) & 1) * AT_STAGEB + fill_off;
            cp16(d,            kf + gkv); cp16(d + 16,            kf + gkv + 8);
            cp16(d + AT_TILEB, vf + gkv); cp16(d + AT_TILEB + 16, vf + gkv + 8);
            cp_commit();
            cp_wait<1>();
        } else {
            cp_wait<0>();
        }
        __syncthreads();

        if (kt * 64 <= qbaseG + 15) {
            const uint32_t uSt = uD + (kt & 1) * AT_STAGEB;
            const uint32_t uKf = uSt, uVf = uSt + AT_TILEB;

            // ---- S = (Qh+Ql) @ K^T ----
            float s[8][4];
#pragma unroll
            for (int t = 0; t < 8; t++)
#pragma unroll
                for (int j = 0; j < 4; j++) s[t][j] = 0.f;

#pragma unroll
            for (int kc = 0; kc < 4; kc++) {
#pragma unroll
                for (int nt2 = 0; nt2 < 4; nt2++) {
                    const uint32_t boff =
                        (uint32_t)((nt2 * 16 + (lg >> 1) * 8 + lr) * APAD + (lg & 1) * 8 + kc * 16) * 2;
                    uint32_t f[4];
                    ldsm_x4(uKf + boff, f);
                    mma_f16(s[nt2 * 2],     qfh[kc], f);
                    mma_f16(s[nt2 * 2 + 1], qfh[kc], f + 2);
                    mma_f16(s[nt2 * 2],     qfl[kc], f);
                    mma_f16(s[nt2 * 2 + 1], qfl[kc], f + 2);
                }
            }

            // ---- block-causal mask ----
            if (kt * 64 + 63 > qbaseG + 7) {
#pragma unroll
                for (int t = 0; t < 8; t++) {
                    const int key = kt * 64 + t * 8 + qd * 2;
                    if (key     > lim0) s[t][0] = -1e30f;
                    if (key + 1 > lim0) s[t][1] = -1e30f;
                    if (key     > lim1) s[t][2] = -1e30f;
                    if (key + 1 > lim1) s[t][3] = -1e30f;
                }
            }

            // ---- online softmax (l from exact fp32 scores) ----
            float mx0 = -1e30f, mx1 = -1e30f;
#pragma unroll
            for (int t = 0; t < 8; t++) {
                mx0 = fmaxf(mx0, fmaxf(s[t][0], s[t][1]));
                mx1 = fmaxf(mx1, fmaxf(s[t][2], s[t][3]));
            }
            mx0 = fmaxf(mx0, __shfl_xor_sync(0xffffffffu, mx0, 1));
            mx0 = fmaxf(mx0, __shfl_xor_sync(0xffffffffu, mx0, 2));
            mx1 = fmaxf(mx1, __shfl_xor_sync(0xffffffffu, mx1, 1));
            mx1 = fmaxf(mx1, __shfl_xor_sync(0xffffffffu, mx1, 2));

            const float mn0 = fmaxf(m0, mx0), mn1 = fmaxf(m1, mx1);
            const float a0 = __expf(m0 - mn0), a1 = __expf(m1 - mn1);
            l0 *= a0; l1 *= a1;
#pragma unroll
            for (int t = 0; t < 8; t++) {
                o[t][0] *= a0; o[t][1] *= a0; o[t][2] *= a1; o[t][3] *= a1;
            }
            float sl0 = 0.f, sl1 = 0.f;
#pragma unroll
            for (int t = 0; t < 8; t++) {
                s[t][0] = __expf(s[t][0] - mn0); s[t][1] = __expf(s[t][1] - mn0);
                s[t][2] = __expf(s[t][2] - mn1); s[t][3] = __expf(s[t][3] - mn1);
                sl0 += s[t][0] + s[t][1];
                sl1 += s[t][2] + s[t][3];
            }
            sl0 += __shfl_xor_sync(0xffffffffu, sl0, 1);
            sl0 += __shfl_xor_sync(0xffffffffu, sl0, 2);
            sl1 += __shfl_xor_sync(0xffffffffu, sl1, 1);
            sl1 += __shfl_xor_sync(0xffffffffu, sl1, 2);
            l0 += sl0; l1 += sl1;
            m0 = mn0; m1 = mn1;

            // ---- pack P single fp16 A-fragments ----
            uint32_t ph[8][2];
#pragma unroll
            for (int t = 0; t < 8; t++) {
                ph[t][0] = pk_h2(s[t][0], s[t][1]);
                ph[t][1] = pk_h2(s[t][2], s[t][3]);
            }

            // ---- O += P @ V (single pass) ----
#pragma unroll
            for (int kc = 0; kc < 4; kc++) {
                uint32_t ah[4] = {ph[2*kc][0], ph[2*kc][1], ph[2*kc+1][0], ph[2*kc+1][1]};
#pragma unroll
                for (int nt2 = 0; nt2 < 4; nt2++) {
                    const uint32_t voff =
                        (uint32_t)((kc * 16 + (lg & 1) * 8 + lr) * APAD + nt2 * 16 + (lg >> 1) * 8) * 2;
                    uint32_t f[4];
                    ldsm_x4_t(uVf + voff, f);
                    mma_f16(o[nt2 * 2],     ah, f);
                    mma_f16(o[nt2 * 2 + 1], ah, f + 2);
                }
            }
        }
        __syncthreads();
    }

    // ---- epilogue: normalize + hi/lo fp16 split write ----
    const float inv0 = 1.f / l0, inv1 = 1.f / l1;
    const int row0 = qbaseG + quad;
    const size_t e0 = (((size_t)(b * S_ + row0)) * NH_ + h) * HD_ + qd * 2;
    const size_t e1 = (((size_t)(b * S_ + row0 + 8)) * NH_ + h) * HD_ + qd * 2;
#pragma unroll
    for (int t = 0; t < 8; t++) {
        float x0 = o[t][0] * inv0, x1 = o[t][1] * inv0;
        float y0 = o[t][2] * inv1, y1 = o[t][3] * inv1;
        float rx0, rx1, ry0, ry1;
        float hx0 = h_hi(x0, &rx0), hx1 = h_hi(x1, &rx1);
        float hy0 = h_hi(y0, &ry0), hy1 = h_hi(y1, &ry1);
        *(uint32_t*)(aoh + e0 + t * 8) = pk_h2(hx0, hx1);
        *(uint32_t*)(aol + e0 + t * 8) = pk_h2(rx0, rx1);
        *(uint32_t*)(aoh + e1 + t * 8) = pk_h2(hy0, hy1);
        *(uint32_t*)(aol + e1 + t * 8) = pk_h2(ry0, ry1);
    }
}

// ---------------------------------------------------------------------------
extern "C" void kernel_launch(void* const* d_in, const int* in_sizes, int n_in,
                              void* d_out, int out_size)
{
    const float* x   = (const float*)d_in[0];
    const float* wq  = (const float*)d_in[1];
    const float* wk  = (const float*)d_in[2];
    const float* wv  = (const float*)d_in[3];
    const float* wo  = (const float*)d_in[4];
    const float* fcc = (const float*)d_in[5];
    const float* fcs = (const float*)d_in[6];
    (void)in_sizes; (void)n_in;

    __half *xh, *xl, *wqf, *wkf, *wvf, *wof;
    __half *qfh, *qfl, *kf, *vf, *aoh, *aol;
    cudaGetSymbolAddress((void**)&xh,  g_xh);
    cudaGetSymbolAddress((void**)&xl,  g_xl);
    cudaGetSymbolAddress((void**)&wqf, g_wqf);
    cudaGetSymbolAddress((void**)&wkf, g_wkf);
    cudaGetSymbolAddress((void**)&wvf, g_wvf);
    cudaGetSymbolAddress((void**)&wof, g_wof);
    cudaGetSymbolAddress((void**)&qfh, g_qfh);
    cudaGetSymbolAddress((void**)&qfl, g_qfl);
    cudaGetSymbolAddress((void**)&kf,  g_kf);
    cudaGetSymbolAddress((void**)&vf,  g_vf);
    cudaGetSymbolAddress((void**)&aoh, g_aoh);
    cudaGetSymbolAddress((void**)&aol, g_aol);

    cudaFuncSetAttribute(hgemm2,    cudaFuncAttributeMaxDynamicSharedMemorySize, HG_SMEM);
    cudaFuncSetAttribute(attn_mma2, cudaFuncAttributeMaxDynamicSharedMemorySize, AT_SMEM);

    const int M = M_;   // 8192

    // input prep
    split_h<<<(M * D_ / 4 + 255) / 256, 256>>>(x, xh, xl, M * D_ / 4);
    trans_conv<<<dim3(D_/32, D_/32), dim3(32, 8)>>>(wq, wqf, D_,   D_);
    trans_conv<<<dim3(D_/64, D_/32), dim3(32, 8)>>>(wk, wkf, D_/2, D_);
    trans_conv<<<dim3(D_/64, D_/32), dim3(32, 8)>>>(wv, wvf, D_/2, D_);
    trans_conv<<<dim3(D_/32, D_/32), dim3(32, 8)>>>(wo, wof, D_,   D_);

    // QKV projections with fused RoPE/convert epilogues
    hgemm2<<<dim3(NH_*HD_/128,  M/128), 256, HG_SMEM>>>(
        xh, xl, wqf, nullptr, qfh, qfl, fcc, fcs, NH_*HD_,  D_, 1, 0.125f);
    hgemm2<<<dim3(NKV_*HD_/128, M/128), 256, HG_SMEM>>>(
        xh, xl, wkf, nullptr, kf, nullptr, fcc, fcs, NKV_*HD_, D_, 2, 1.0f);
    hgemm2<<<dim3(NKV_*HD_/128, M/128), 256, HG_SMEM>>>(
        xh, xl, wvf, nullptr, vf, nullptr, fcc, fcs, NKV_*HD_, D_, 3, 1.0f);

    // Attention
    attn_mma2<<<dim3(S_/128, NH_, B_), 256, AT_SMEM>>>(qfh, qfl, kf, vf, aoh, aol);

    // Output projection (fp32 out)
    hgemm2<<<dim3(D_/128, M/128), 256, HG_SMEM>>>(
        aoh, aol, wof, (float*)d_out, nullptr, nullptr, fcc, fcs, D_, D_, 0, 1.0f);
    (void)out_size;
}

// round 16
// speedup vs baseline: 4.9199x; 1.2204x over previous
#include <cuda_runtime.h>
#include <cuda_fp16.h>
#include <math.h>
#include <stdint.h>

#define B_ 8
#define S_ 1024
#define D_ 1024
#define NH_ 16
#define NKV_ 8
#define HD_ 64
#define M_ (B_*S_)

// ---------------------------------------------------------------------------
// Scratch (allocation-free rule: __device__ globals)
// ---------------------------------------------------------------------------
__device__ __half g_xh[M_*D_],  g_xl[M_*D_];            // x hi/lo fp16
__device__ __half g_wqf[D_*D_];                         // weights^T single fp16
__device__ __half g_wkf[(D_/2)*D_];
__device__ __half g_wvf[(D_/2)*D_];
__device__ __half g_wof[D_*D_];
__device__ __half g_qfh[M_*NH_*HD_], g_qfl[M_*NH_*HD_]; // roped q hi/lo (x0.125)
__device__ __half g_kf[M_*NKV_*HD_];                    // roped k single fp16
__device__ __half g_vf[M_*NKV_*HD_];                    // v single fp16
__device__ __half g_aof[M_*NH_*HD_];                    // attn out single fp16

// ---------------------------------------------------------------------------
// helpers
// ---------------------------------------------------------------------------
__device__ __forceinline__ uint32_t smem_u32(const void* p) {
    uint32_t a;
    asm("{ .reg .u64 t; cvta.to.shared.u64 t, %1; cvt.u32.u64 %0, t; }" : "=r"(a) : "l"(p));
    return a;
}
__device__ __forceinline__ void ldsm_x4(uint32_t addr, uint32_t* d) {
    asm volatile("ldmatrix.sync.aligned.m8n8.x4.shared.b16 {%0,%1,%2,%3}, [%4];"
                 : "=r"(d[0]), "=r"(d[1]), "=r"(d[2]), "=r"(d[3]) : "r"(addr));
}
__device__ __forceinline__ void ldsm_x4_t(uint32_t addr, uint32_t* d) {
    asm volatile("ldmatrix.sync.aligned.m8n8.x4.trans.shared.b16 {%0,%1,%2,%3}, [%4];"
                 : "=r"(d[0]), "=r"(d[1]), "=r"(d[2]), "=r"(d[3]) : "r"(addr));
}
__device__ __forceinline__ void mma_f16(float* c, const uint32_t* a, const uint32_t* b) {
    asm volatile(
        "mma.sync.aligned.m16n8k16.row.col.f32.f16.f16.f32 "
        "{%0,%1,%2,%3}, {%4,%5,%6,%7}, {%8,%9}, {%0,%1,%2,%3};"
        : "+f"(c[0]), "+f"(c[1]), "+f"(c[2]), "+f"(c[3])
        : "r"(a[0]), "r"(a[1]), "r"(a[2]), "r"(a[3]), "r"(b[0]), "r"(b[1]));
}
__device__ __forceinline__ void cp16(uint32_t dst, const void* src) {
    asm volatile("cp.async.cg.shared.global [%0], [%1], 16;" :: "r"(dst), "l"(src) : "memory");
}
__device__ __forceinline__ void cp_commit() {
    asm volatile("cp.async.commit_group;" ::: "memory");
}
template<int N> __device__ __forceinline__ void cp_wait() {
    asm volatile("cp.async.wait_group %0;" :: "n"(N) : "memory");
}
__device__ __forceinline__ uint32_t pk_h2(float lo, float hi) {
    __half2 t;
    t.x = __float2half_rn(lo);
    t.y = __float2half_rn(hi);
    return *reinterpret_cast<uint32_t*>(&t);
}
__device__ __forceinline__ float h_hi(float x, float* rem) {
    __half h = __float2half_rn(x);
    float hf = __half2float(h);
    *rem = x - hf;
    return hf;
}

// ---------------------------------------------------------------------------
// elementwise: fp32 -> hi/lo fp16 (for x)
// ---------------------------------------------------------------------------
__global__ void split_h(const float* __restrict__ src,
                        __half* __restrict__ dh,
                        __half* __restrict__ dl, int n4)
{
    int i = blockIdx.x * blockDim.x + threadIdx.x;
    if (i >= n4) return;
    float4 f = *(const float4*)(src + (size_t)i * 4);
    float r0, r1, r2, r3;
    float h0 = h_hi(f.x, &r0), h1 = h_hi(f.y, &r1);
    float h2 = h_hi(f.z, &r2), h3 = h_hi(f.w, &r3);
    *(uint2*)(dh + (size_t)i * 4) = make_uint2(pk_h2(h0, h1), pk_h2(h2, h3));
    *(uint2*)(dl + (size_t)i * 4) = make_uint2(pk_h2(r0, r1), pk_h2(r2, r3));
}

// ---------------------------------------------------------------------------
// transpose + single fp16 convert: W[K,N] fp32 -> T[N,K] fp16
// ---------------------------------------------------------------------------
__global__ void trans_conv(const float* __restrict__ W,
                           __half* __restrict__ Tf, int N, int K)
{
    __shared__ float t[32][33];
    const int n0 = blockIdx.x * 32, k0 = blockIdx.y * 32;
    const int tx = threadIdx.x, ty = threadIdx.y;
#pragma unroll
    for (int i = 0; i < 4; i++)
        t[ty + i * 8][tx] = W[(size_t)(k0 + ty + i * 8) * N + n0 + tx];
    __syncthreads();
#pragma unroll
    for (int i = 0; i < 4; i++) {
        size_t o = (size_t)(n0 + ty + i * 8) * K + k0 + tx;
        Tf[o] = __float2half_rn(t[tx][ty + i * 8]);
    }
}

// ---------------------------------------------------------------------------
// HMMA GEMM: (Ah [+ Al if npass==2]) x single-fp16 B^T, cp.async 2-stage.
// Epilogue modes: 0 fp32 C | 1 RoPE+scale+hi/lo fp16 | 2 RoPE+fp16 | 3 fp16
// ---------------------------------------------------------------------------
#define LDPAD 40
#define HG_TILEB (128 * LDPAD * 2)     // 10240
#define HG_STAGEB (3 * HG_TILEB)       // 30720
#define HG_SMEM (2 * HG_STAGEB)        // 61440

__global__ __launch_bounds__(256, 2) void hgemm2(const __half* __restrict__ Ah,
                                                 const __half* __restrict__ Al,
                                                 const __half* __restrict__ Bf,
                                                 float* __restrict__ C32,
                                                 __half* __restrict__ Ch,
                                                 __half* __restrict__ Cl,
                                                 const float* __restrict__ cs,
                                                 const float* __restrict__ sn,
                                                 int N, int K, int mode, float scale,
                                                 int npass)
{
    extern __shared__ __align__(16) char dsm[];
    const uint32_t uD = smem_u32(dsm);

    const int tid = threadIdx.x, lane = tid & 31, wid = tid >> 5;
    const int bn = blockIdx.x, bm = blockIdx.y;
    const int warp_m = (wid & 1) * 64;
    const int warp_n = (wid >> 1) * 32;

    const int row  = tid >> 1;
    const int half = tid & 1;
    const __half* pAh = Ah + (size_t)(bm * 128 + row) * K + half * 16;
    const __half* pAl = Al + (size_t)(bm * 128 + row) * K + half * 16;
    const __half* pBf = Bf + (size_t)(bn * 128 + row) * K + half * 16;
    const uint32_t fill_off = (uint32_t)(row * LDPAD + half * 16) * 2;

    const int g = lane >> 3, r = lane & 7;
    uint32_t aoff[4], boff[2];
#pragma unroll
    for (int mt = 0; mt < 4; mt++)
        aoff[mt] = ((warp_m + mt * 16 + (g & 1) * 8 + r) * LDPAD + (g >> 1) * 8) * 2;
#pragma unroll
    for (int nt2 = 0; nt2 < 2; nt2++)
        boff[nt2] = ((warp_n + nt2 * 16 + (g >> 1) * 8 + r) * LDPAD + (g & 1) * 8) * 2;

    float acc[4][4][4];
#pragma unroll
    for (int i = 0; i < 4; i++)
#pragma unroll
        for (int j = 0; j < 4; j++)
#pragma unroll
            for (int t = 0; t < 4; t++) acc[i][j][t] = 0.f;

    const int NCH = K / 32;

    // prologue: stage 0
    {
        const uint32_t d = uD + fill_off;
        cp16(d,                pAh); cp16(d + 16,                pAh + 8);
        if (npass == 2) { cp16(d + HG_TILEB, pAl); cp16(d + HG_TILEB + 16, pAl + 8); }
        cp16(d + 2 * HG_TILEB, pBf); cp16(d + 2 * HG_TILEB + 16, pBf + 8);
        cp_commit();
    }

    for (int ch = 0; ch < NCH; ch++) {
        if (ch + 1 < NCH) {
            const int k1 = (ch + 1) * 32;
            const uint32_t d = uD + ((ch + 1) & 1) * HG_STAGEB + fill_off;
            cp16(d,                pAh + k1); cp16(d + 16,                pAh + k1 + 8);
            if (npass == 2) {
                cp16(d + HG_TILEB, pAl + k1); cp16(d + HG_TILEB + 16, pAl + k1 + 8);
            }
            cp16(d + 2 * HG_TILEB, pBf + k1); cp16(d + 2 * HG_TILEB + 16, pBf + k1 + 8);
            cp_commit();
            cp_wait<1>();
        } else {
            cp_wait<0>();
        }
        __syncthreads();

        const uint32_t uSt = uD + (ch & 1) * HG_STAGEB;
        const uint32_t uAh = uSt, uAl = uSt + HG_TILEB, uBf = uSt + 2 * HG_TILEB;
#pragma unroll
        for (int ks = 0; ks < 2; ks++) {
            const uint32_t kadd = ks * 32;
            uint32_t bfr[2][4], afr[4][4];
#pragma unroll
            for (int nt2 = 0; nt2 < 2; nt2++) ldsm_x4(uBf + boff[nt2] + kadd, bfr[nt2]);
#pragma unroll
            for (int mt = 0; mt < 4; mt++) ldsm_x4(uAh + aoff[mt] + kadd, afr[mt]);
#pragma unroll
            for (int mt = 0; mt < 4; mt++)
#pragma unroll
                for (int nt = 0; nt < 4; nt++)
                    mma_f16(acc[mt][nt], afr[mt], bfr[nt >> 1] + (nt & 1) * 2);
            if (npass == 2) {
#pragma unroll
                for (int mt = 0; mt < 4; mt++) ldsm_x4(uAl + aoff[mt] + kadd, afr[mt]);
#pragma unroll
                for (int mt = 0; mt < 4; mt++)
#pragma unroll
                    for (int nt = 0; nt < 4; nt++)
                        mma_f16(acc[mt][nt], afr[mt], bfr[nt >> 1] + (nt & 1) * 2);
            }
        }
        __syncthreads();
    }

    // ---- epilogue ----
    const int erow = lane >> 2;
    const int ecol = (lane & 3) * 2;
#pragma unroll
    for (int mt = 0; mt < 4; mt++) {
#pragma unroll
        for (int nt = 0; nt < 4; nt++) {
            const int gr = bm * 128 + warp_m + mt * 16 + erow;
            const int gc = bn * 128 + warp_n + nt * 8 + ecol;
            float a0 = acc[mt][nt][0], a1 = acc[mt][nt][1];
            float a2 = acc[mt][nt][2], a3 = acc[mt][nt][3];
            if (mode == 0) {
                float* Cr = C32 + (size_t)gr * N + gc;
                *(float2*)Cr                   = make_float2(a0, a1);
                *(float2*)(Cr + 8 * (size_t)N) = make_float2(a2, a3);
            } else if (mode == 3) {
                *(uint32_t*)(Ch + (size_t)gr * N + gc)       = pk_h2(a0, a1);
                *(uint32_t*)(Ch + (size_t)(gr + 8) * N + gc) = pk_h2(a2, a3);
            } else {
                const int d2 = (gc & 63) >> 1;
                const int s0 = gr & (S_ - 1), s1 = (gr + 8) & (S_ - 1);
                const float c0 = cs[s0 * 32 + d2], t0 = sn[s0 * 32 + d2];
                const float c1 = cs[s1 * 32 + d2], t1 = sn[s1 * 32 + d2];
                float r0 = (a0 * c0 - a1 * t0) * scale;
                float r1 = (a0 * t0 + a1 * c0) * scale;
                float r2 = (a2 * c1 - a3 * t1) * scale;
                float r3 = (a2 * t1 + a3 * c1) * scale;
                if (mode == 2) {
                    *(uint32_t*)(Ch + (size_t)gr * N + gc)       = pk_h2(r0, r1);
                    *(uint32_t*)(Ch + (size_t)(gr + 8) * N + gc) = pk_h2(r2, r3);
                } else {
                    float l0, l1, l2, l3;
                    float h0 = h_hi(r0, &l0), h1 = h_hi(r1, &l1);
                    float h2 = h_hi(r2, &l2), h3 = h_hi(r3, &l3);
                    *(uint32_t*)(Ch + (size_t)gr * N + gc)       = pk_h2(h0, h1);
                    *(uint32_t*)(Cl + (size_t)gr * N + gc)       = pk_h2(l0, l1);
                    *(uint32_t*)(Ch + (size_t)(gr + 8) * N + gc) = pk_h2(h2, h3);
                    *(uint32_t*)(Cl + (size_t)(gr + 8) * N + gc) = pk_h2(l2, l3);
                }
            }
        }
    }
}

// ---------------------------------------------------------------------------
// HMMA flash attention, fp16: Q 2-pass (hi/lo); K,V,P single fp16.
// cp.async 2-stage K/V pipeline; Q staged once. Output: single fp16.
// ---------------------------------------------------------------------------
#define APAD 72
#define TILE_E (64 * APAD)
#define AT_TILEB (TILE_E * 2)          // 9216
#define AT_STAGEB (2 * AT_TILEB)       // 18432
#define AT_SMEM (2 * AT_STAGEB)        // 36864

__global__ __launch_bounds__(256) void attn_mma2(const __half* __restrict__ qh,
                                                 const __half* __restrict__ ql,
                                                 const __half* __restrict__ kf,
                                                 const __half* __restrict__ vf,
                                                 __half* __restrict__ aof)
{
    extern __shared__ __align__(16) char dsm[];
    __half* sm = (__half*)dsm;
    const uint32_t uD = smem_u32(dsm);

    const int tid = threadIdx.x, lane = tid & 31, wid = tid >> 5;
    const int qt = blockIdx.x, h = blockIdx.y, b = blockIdx.z;
    const int kvh = h >> 1;
    const int lg = lane >> 3, lr = lane & 7;
    const int quad = lane >> 2, qd = lane & 3;

    // ---- Q stage ----
    {
        const int row = tid >> 1, half = tid & 1;
        const size_t gq = (((size_t)(b * S_ + qt * 128 + row)) * NH_ + h) * HD_ + half * 32;
        __half* dh = sm + row * APAD + half * 32;
        __half* dl = sm + AT_STAGEB / 2 + row * APAD + half * 32;
#pragma unroll
        for (int i = 0; i < 4; i++) *(uint4*)(dh + i * 8) = *(const uint4*)(qh + gq + i * 8);
#pragma unroll
        for (int i = 0; i < 4; i++) *(uint4*)(dl + i * 8) = *(const uint4*)(ql + gq + i * 8);
    }
    __syncthreads();

    uint32_t qfh[4][4], qfl[4][4];
    {
        const int rowa = wid * 16 + (lg & 1) * 8 + lr;
#pragma unroll
        for (int kc = 0; kc < 4; kc++) {
            const uint32_t off = (uint32_t)(rowa * APAD + (lg >> 1) * 8 + kc * 16) * 2;
            ldsm_x4(uD + off, qfh[kc]);
            ldsm_x4(uD + AT_STAGEB + off, qfl[kc]);
        }
    }
    __syncthreads();

    float o[8][4];
#pragma unroll
    for (int t = 0; t < 8; t++)
#pragma unroll
        for (int j = 0; j < 4; j++) o[t][j] = 0.f;
    float m0 = -1e30f, m1 = -1e30f, l0 = 0.f, l1 = 0.f;

    const int qbaseG = qt * 128 + wid * 16;
    const int lim0 = (qbaseG + quad) | 7;
    const int lim1 = (qbaseG + quad + 8) | 7;
    const int ntiles = 2 * qt + 2;

    const int krow = tid >> 2, kc4 = (tid & 3) * 16;
    const uint32_t fill_off = (uint32_t)(krow * APAD + kc4) * 2;

    {
        const size_t gkv = (((size_t)(b * S_ + krow)) * NKV_ + kvh) * HD_ + kc4;
        const uint32_t d = uD + fill_off;
        cp16(d,            kf + gkv); cp16(d + 16,            kf + gkv + 8);
        cp16(d + AT_TILEB, vf + gkv); cp16(d + AT_TILEB + 16, vf + gkv + 8);
        cp_commit();
    }

    for (int kt = 0; kt < ntiles; kt++) {
        if (kt + 1 < ntiles) {
            const size_t gkv = (((size_t)(b * S_ + (kt + 1) * 64 + krow)) * NKV_ + kvh) * HD_ + kc4;
            const uint32_t d = uD + ((kt + 1) & 1) * AT_STAGEB + fill_off;
            cp16(d,            kf + gkv); cp16(d + 16,            kf + gkv + 8);
            cp16(d + AT_TILEB, vf + gkv); cp16(d + AT_TILEB + 16, vf + gkv + 8);
            cp_commit();
            cp_wait<1>();
        } else {
            cp_wait<0>();
        }
        __syncthreads();

        if (kt * 64 <= qbaseG + 15) {
            const uint32_t uSt = uD + (kt & 1) * AT_STAGEB;
            const uint32_t uKf = uSt, uVf = uSt + AT_TILEB;

            // ---- S = (Qh+Ql) @ K^T ----
            float s[8][4];
#pragma unroll
            for (int t = 0; t < 8; t++)
#pragma unroll
                for (int j = 0; j < 4; j++) s[t][j] = 0.f;

#pragma unroll
            for (int kc = 0; kc < 4; kc++) {
#pragma unroll
                for (int nt2 = 0; nt2 < 4; nt2++) {
                    const uint32_t boff =
                        (uint32_t)((nt2 * 16 + (lg >> 1) * 8 + lr) * APAD + (lg & 1) * 8 + kc * 16) * 2;
                    uint32_t f[4];
                    ldsm_x4(uKf + boff, f);
                    mma_f16(s[nt2 * 2],     qfh[kc], f);
                    mma_f16(s[nt2 * 2 + 1], qfh[kc], f + 2);
                    mma_f16(s[nt2 * 2],     qfl[kc], f);
                    mma_f16(s[nt2 * 2 + 1], qfl[kc], f + 2);
                }
            }

            // ---- block-causal mask ----
            if (kt * 64 + 63 > qbaseG + 7) {
#pragma unroll
                for (int t = 0; t < 8; t++) {
                    const int key = kt * 64 + t * 8 + qd * 2;
                    if (key     > lim0) s[t][0] = -1e30f;
                    if (key + 1 > lim0) s[t][1] = -1e30f;
                    if (key     > lim1) s[t][2] = -1e30f;
                    if (key + 1 > lim1) s[t][3] = -1e30f;
                }
            }

            // ---- online softmax ----
            float mx0 = -1e30f, mx1 = -1e30f;
#pragma unroll
            for (int t = 0; t < 8; t++) {
                mx0 = fmaxf(mx0, fmaxf(s[t][0], s[t][1]));
                mx1 = fmaxf(mx1, fmaxf(s[t][2], s[t][3]));
            }
            mx0 = fmaxf(mx0, __shfl_xor_sync(0xffffffffu, mx0, 1));
            mx0 = fmaxf(mx0, __shfl_xor_sync(0xffffffffu, mx0, 2));
            mx1 = fmaxf(mx1, __shfl_xor_sync(0xffffffffu, mx1, 1));
            mx1 = fmaxf(mx1, __shfl_xor_sync(0xffffffffu, mx1, 2));

            const float mn0 = fmaxf(m0, mx0), mn1 = fmaxf(m1, mx1);
            const float a0 = __expf(m0 - mn0), a1 = __expf(m1 - mn1);
            l0 *= a0; l1 *= a1;
#pragma unroll
            for (int t = 0; t < 8; t++) {
                o[t][0] *= a0; o[t][1] *= a0; o[t][2] *= a1; o[t][3] *= a1;
            }
            float sl0 = 0.f, sl1 = 0.f;
#pragma unroll
            for (int t = 0; t < 8; t++) {
                s[t][0] = __expf(s[t][0] - mn0); s[t][1] = __expf(s[t][1] - mn0);
                s[t][2] = __expf(s[t][2] - mn1); s[t][3] = __expf(s[t][3] - mn1);
                sl0 += s[t][0] + s[t][1];
                sl1 += s[t][2] + s[t][3];
            }
            sl0 += __shfl_xor_sync(0xffffffffu, sl0, 1);
            sl0 += __shfl_xor_sync(0xffffffffu, sl0, 2);
            sl1 += __shfl_xor_sync(0xffffffffu, sl1, 1);
            sl1 += __shfl_xor_sync(0xffffffffu, sl1, 2);
            l0 += sl0; l1 += sl1;
            m0 = mn0; m1 = mn1;

            // ---- pack P single fp16 A-fragments ----
            uint32_t ph[8][2];
#pragma unroll
            for (int t = 0; t < 8; t++) {
                ph[t][0] = pk_h2(s[t][0], s[t][1]);
                ph[t][1] = pk_h2(s[t][2], s[t][3]);
            }

            // ---- O += P @ V (single pass) ----
#pragma unroll
            for (int kc = 0; kc < 4; kc++) {
                uint32_t ah[4] = {ph[2*kc][0], ph[2*kc][1], ph[2*kc+1][0], ph[2*kc+1][1]};
#pragma unroll
                for (int nt2 = 0; nt2 < 4; nt2++) {
                    const uint32_t voff =
                        (uint32_t)((kc * 16 + (lg & 1) * 8 + lr) * APAD + nt2 * 16 + (lg >> 1) * 8) * 2;
                    uint32_t f[4];
                    ldsm_x4_t(uVf + voff, f);
                    mma_f16(o[nt2 * 2],     ah, f);
                    mma_f16(o[nt2 * 2 + 1], ah, f + 2);
                }
            }
        }
        __syncthreads();
    }

    // ---- epilogue: normalize + single fp16 write ----
    const float inv0 = 1.f / l0, inv1 = 1.f / l1;
    const int row0 = qbaseG + quad;
    const size_t e0 = (((size_t)(b * S_ + row0)) * NH_ + h) * HD_ + qd * 2;
    const size_t e1 = (((size_t)(b * S_ + row0 + 8)) * NH_ + h) * HD_ + qd * 2;
#pragma unroll
    for (int t = 0; t < 8; t++) {
        *(uint32_t*)(aof + e0 + t * 8) = pk_h2(o[t][0] * inv0, o[t][1] * inv0);
        *(uint32_t*)(aof + e1 + t * 8) = pk_h2(o[t][2] * inv1, o[t][3] * inv1);
    }
}

// ---------------------------------------------------------------------------
extern "C" void kernel_launch(void* const* d_in, const int* in_sizes, int n_in,
                              void* d_out, int out_size)
{
    const float* x   = (const float*)d_in[0];
    const float* wq  = (const float*)d_in[1];
    const float* wk  = (const float*)d_in[2];
    const float* wv  = (const float*)d_in[3];
    const float* wo  = (const float*)d_in[4];
    const float* fcc = (const float*)d_in[5];
    const float* fcs = (const float*)d_in[6];
    (void)in_sizes; (void)n_in;

    __half *xh, *xl, *wqf, *wkf, *wvf, *wof;
    __half *qfh, *qfl, *kf, *vf, *aof;
    cudaGetSymbolAddress((void**)&xh,  g_xh);
    cudaGetSymbolAddress((void**)&xl,  g_xl);
    cudaGetSymbolAddress((void**)&wqf, g_wqf);
    cudaGetSymbolAddress((void**)&wkf, g_wkf);
    cudaGetSymbolAddress((void**)&wvf, g_wvf);
    cudaGetSymbolAddress((void**)&wof, g_wof);
    cudaGetSymbolAddress((void**)&qfh, g_qfh);
    cudaGetSymbolAddress((void**)&qfl, g_qfl);
    cudaGetSymbolAddress((void**)&kf,  g_kf);
    cudaGetSymbolAddress((void**)&vf,  g_vf);
    cudaGetSymbolAddress((void**)&aof, g_aof);

    cudaFuncSetAttribute(hgemm2,    cudaFuncAttributeMaxDynamicSharedMemorySize, HG_SMEM);
    cudaFuncSetAttribute(attn_mma2, cudaFuncAttributeMaxDynamicSharedMemorySize, AT_SMEM);

    const int M = M_;   // 8192

    // input prep
    split_h<<<(M * D_ / 4 + 255) / 256, 256>>>(x, xh, xl, M * D_ / 4);
    trans_conv<<<dim3(D_/32, D_/32), dim3(32, 8)>>>(wq, wqf, D_,   D_);
    trans_conv<<<dim3(D_/64, D_/32), dim3(32, 8)>>>(wk, wkf, D_/2, D_);
    trans_conv<<<dim3(D_/64, D_/32), dim3(32, 8)>>>(wv, wvf, D_/2, D_);
    trans_conv<<<dim3(D_/32, D_/32), dim3(32, 8)>>>(wo, wof, D_,   D_);

    // QKV projections with fused RoPE/convert epilogues
    hgemm2<<<dim3(NH_*HD_/128,  M/128), 256, HG_SMEM>>>(
        xh, xl, wqf, nullptr, qfh, qfl, fcc, fcs, NH_*HD_,  D_, 1, 0.125f, 2);
    hgemm2<<<dim3(NKV_*HD_/128, M/128), 256, HG_SMEM>>>(
        xh, xl, wkf, nullptr, kf, nullptr, fcc, fcs, NKV_*HD_, D_, 2, 1.0f, 2);
    hgemm2<<<dim3(NKV_*HD_/128, M/128), 256, HG_SMEM>>>(
        xh, xh, wvf, nullptr, vf, nullptr, fcc, fcs, NKV_*HD_, D_, 3, 1.0f, 1);

    // Attention
    attn_mma2<<<dim3(S_/128, NH_, B_), 256, AT_SMEM>>>(qfh, qfl, kf, vf, aof);

    // Output projection (single-pass A, fp32 out)
    hgemm2<<<dim3(D_/128, M/128), 256, HG_SMEM>>>(
        aof, aof, wof, (float*)d_out, nullptr, nullptr, fcc, fcs, D_, D_, 0, 1.0f, 1);
    (void)out_size;
}